// round 15
// baseline (speedup 1.0000x reference)
#include <cuda_runtime.h>
#include <cuda_bf16.h>
#include <cstdint>

#define NNODES 50000
#define HID    128
#define MAXD   16
#define NGRAPH 50
#define NCLS   10
#define GRUH   32
#define MAXB   3400

// ---------------- scratch ----------------
__device__ __nv_bfloat16 g_Pb [(size_t)NNODES * 512];
__device__ __nv_bfloat16 g_featB[(size_t)NNODES * HID];
__device__ __nv_bfloat16 g_hTb [(size_t)NNODES * HID];
__device__ __nv_bfloat16 g_h1b [(size_t)NNODES * HID];
__device__ __nv_bfloat16 g_aggB[(size_t)NNODES * HID];
__device__ __nv_bfloat16 g_h2b [(size_t)NNODES * HID];
__device__ float g_gh [(size_t)NNODES * 96];
__device__ float g_o32[(size_t)NNODES * GRUH];
// fused (kt, kt+4) weight fragments: uint4 = {frag(kt).xy, frag(kt+4).xy}
__device__ uint4 g_WfP4   [8192];   // N=512 (64 groups), kt-major
__device__ uint4 g_WfSelf4[2048];   // N=128
__device__ uint4 g_WfNeigh4[2048];
__device__ uint4 g_WfGc4  [2048];
__device__ uint4 g_WfGru4 [1536];   // N=96
__device__ uint4 g_Wfrag4[256 * 32];         // lstm Whh fragments, E/O fused
__device__ float4 g_biasF[HID];              // (bi,bf,bg,bo)
__device__ float g_pp[NGRAPH][4][32];
__device__ int   g_pc[NGRAPH][4];
// degree bucketing
__device__ int g_order[NNODES];
__device__ int g_bincnt[16];
__device__ int g_binoff[16];
__device__ int g_batch_start[MAXB];
__device__ int g_batch_info[MAXB];
__device__ int g_nbatch;

// ---------------- helpers ----------------
__device__ __forceinline__ float sigf(float x) {
    x = fminf(fmaxf(x, -30.f), 30.f);
    return __fdividef(1.f, 1.f + __expf(-x));
}
__device__ __forceinline__ float tanh_(float x) {
    x = fminf(fmaxf(x, -15.f), 15.f);
    float e = __expf(-2.f * x);
    return __fdividef(1.f - e, 1.f + e);
}
__device__ __forceinline__ float tanhap(float x) {
    float y; asm("tanh.approx.f32 %0, %1;" : "=f"(y) : "f"(x)); return y;
}
__device__ __forceinline__ float sigt(float x) { return fmaf(tanhap(x * 0.5f), 0.5f, 0.5f); }
__device__ __forceinline__ unsigned bf16u(float x) {
    __nv_bfloat16 b = __float2bfloat16(x);
    return (unsigned)*reinterpret_cast<unsigned short*>(&b);
}
__device__ __forceinline__ float blo(unsigned v) { return __uint_as_float(v << 16); }
__device__ __forceinline__ float bhi(unsigned v) { return __uint_as_float(v & 0xFFFF0000u); }

__host__ __device__ __forceinline__ int phys2row(int p) {
    int pb = p >> 4, rem = p & 15;
    int gamma, aa;
    if (rem < 8) { aa = rem >> 1; gamma = (rem & 1) ? 1 : 0; }
    else         { aa = (rem - 8) >> 1; gamma = (rem & 1) ? 3 : 2; }
    return gamma * HID + pb * 4 + aa;
}

__device__ __forceinline__ void mma16816(float* d, const unsigned* a, unsigned b0, unsigned b1) {
    asm volatile(
        "mma.sync.aligned.m16n8k16.row.col.f32.bf16.bf16.f32 "
        "{%0,%1,%2,%3}, {%4,%5,%6,%7}, {%8,%9}, {%0,%1,%2,%3};"
        : "+f"(d[0]), "+f"(d[1]), "+f"(d[2]), "+f"(d[3])
        : "r"(a[0]), "r"(a[1]), "r"(a[2]), "r"(a[3]), "r"(b0), "r"(b1));
}

__device__ __forceinline__ void ldsm4(unsigned* r, const void* p) {
    unsigned addr = (unsigned)__cvta_generic_to_shared(p);
    asm volatile("ldmatrix.sync.aligned.m8n8.x4.shared.b16 {%0,%1,%2,%3}, [%4];"
                 : "=r"(r[0]), "=r"(r[1]), "=r"(r[2]), "=r"(r[3]) : "r"(addr));
}

// ---------------- prep: all weight packing (+ bincnt reset) ----------------
__global__ void prep_kernel(const float* __restrict__ Wih,
                            const float* __restrict__ Whh,
                            const float* __restrict__ bih,
                            const float* __restrict__ bhh,
                            const float* __restrict__ Wself,
                            const float* __restrict__ Wneigh,
                            const float* __restrict__ Wgc,
                            const float* __restrict__ Wgru) {
    int idx = blockIdx.x * blockDim.x + threadIdx.x;
    int l = idx & 31, t = idx >> 5;
    if (idx < 16) g_bincnt[idx] = 0;
    if (idx < 8192) {                  // P fused: kt 0..3 paired with kt+4
        int kt = t >> 6, gg = t & 63;
        int n = gg * 8 + (l >> 2);
        int r = phys2row(n) * HID;
        int ka = kt * 16 + (l & 3) * 2;
        int kb = ka + 64;
        uint4 v;
        v.x = bf16u(Wih[r + ka])     | (bf16u(Wih[r + ka + 1]) << 16);
        v.y = bf16u(Wih[r + ka + 8]) | (bf16u(Wih[r + ka + 9]) << 16);
        v.z = bf16u(Wih[r + kb])     | (bf16u(Wih[r + kb + 1]) << 16);
        v.w = bf16u(Wih[r + kb + 8]) | (bf16u(Wih[r + kb + 9]) << 16);
        g_WfP4[idx] = v;
    }
    if (idx < 2048) {                  // Self/Neigh/Gc fused (K-major source)
        int kt = t >> 4, gg = t & 15;
        int n = gg * 8 + (l >> 2);
        int ka = kt * 16 + (l & 3) * 2;
        int kb = ka + 64;
        uint4 v;
        v.x = bf16u(Wself[ka * HID + n])       | (bf16u(Wself[(ka + 1) * HID + n]) << 16);
        v.y = bf16u(Wself[(ka + 8) * HID + n]) | (bf16u(Wself[(ka + 9) * HID + n]) << 16);
        v.z = bf16u(Wself[kb * HID + n])       | (bf16u(Wself[(kb + 1) * HID + n]) << 16);
        v.w = bf16u(Wself[(kb + 8) * HID + n]) | (bf16u(Wself[(kb + 9) * HID + n]) << 16);
        g_WfSelf4[idx] = v;
        v.x = bf16u(Wneigh[ka * HID + n])       | (bf16u(Wneigh[(ka + 1) * HID + n]) << 16);
        v.y = bf16u(Wneigh[(ka + 8) * HID + n]) | (bf16u(Wneigh[(ka + 9) * HID + n]) << 16);
        v.z = bf16u(Wneigh[kb * HID + n])       | (bf16u(Wneigh[(kb + 1) * HID + n]) << 16);
        v.w = bf16u(Wneigh[(kb + 8) * HID + n]) | (bf16u(Wneigh[(kb + 9) * HID + n]) << 16);
        g_WfNeigh4[idx] = v;
        v.x = bf16u(Wgc[ka * HID + n])       | (bf16u(Wgc[(ka + 1) * HID + n]) << 16);
        v.y = bf16u(Wgc[(ka + 8) * HID + n]) | (bf16u(Wgc[(ka + 9) * HID + n]) << 16);
        v.z = bf16u(Wgc[kb * HID + n])       | (bf16u(Wgc[(kb + 1) * HID + n]) << 16);
        v.w = bf16u(Wgc[(kb + 8) * HID + n]) | (bf16u(Wgc[(kb + 9) * HID + n]) << 16);
        g_WfGc4[idx] = v;
    }
    if (idx < 1536) {                  // GRU fused (row-major source)
        int kt = t / 12, gg = t % 12;
        int n = gg * 8 + (l >> 2);
        int ka = kt * 16 + (l & 3) * 2;
        int kb = ka + 64;
        const float* wr = Wgru + (size_t)n * HID;
        uint4 v;
        v.x = bf16u(wr[ka])     | (bf16u(wr[ka + 1]) << 16);
        v.y = bf16u(wr[ka + 8]) | (bf16u(wr[ka + 9]) << 16);
        v.z = bf16u(wr[kb])     | (bf16u(wr[kb + 1]) << 16);
        v.w = bf16u(wr[kb + 8]) | (bf16u(wr[kb + 9]) << 16);
        g_WfGru4[idx] = v;
    }
    if (idx < 512 * 32) {
        int t_id = t, lane = l;
        int kt = t_id >> 6, ntg = t_id & 63;
        int p = ntg * 8 + (lane >> 2);
        int wrow = phys2row(p);
        int k0 = kt * 16 + (lane & 3) * 2;
        const float* wr = Whh + (size_t)wrow * HID;
        uint2 v;
        v.x = bf16u(wr[k0])     | (bf16u(wr[k0 + 1]) << 16);
        v.y = bf16u(wr[k0 + 8]) | (bf16u(wr[k0 + 9]) << 16);
        int chunk = ntg >> 4, nt = ntg & 15;
        int pp = nt >> 1, isO = nt & 1;
        int dst = (((kt << 5) | (chunk << 3) | pp) * 32 + lane) * 2 + isO;
        ((uint2*)g_Wfrag4)[dst] = v;
    }
    if (idx < HID) {
        g_biasF[idx] = make_float4(bih[idx] + bhh[idx],
                                   bih[HID + idx] + bhh[HID + idx],
                                   bih[2 * HID + idx] + bhh[2 * HID + idx],
                                   bih[3 * HID + idx] + bhh[3 * HID + idx]);
    }
}

// ------- hist + feature->bf16 fused -------
__global__ void k_hist_f2b(const int* __restrict__ deg,
                           const float* __restrict__ src,
                           __nv_bfloat16* __restrict__ dst) {
    __shared__ int h[16];
    if (threadIdx.x < 16) h[threadIdx.x] = 0;
    __syncthreads();
    int stride = gridDim.x * blockDim.x;
    for (int i = blockIdx.x * blockDim.x + threadIdx.x; i < NNODES; i += stride)
        atomicAdd(&h[deg[i] - 1], 1);
    const int n4 = NNODES * HID / 4;
    for (int i = blockIdx.x * blockDim.x + threadIdx.x; i < n4; i += stride) {
        float4 v = ((const float4*)src)[i];
        uint2 o;
        o.x = bf16u(v.x) | (bf16u(v.y) << 16);
        o.y = bf16u(v.z) | (bf16u(v.w) << 16);
        ((uint2*)dst)[i] = o;
    }
    __syncthreads();
    if (threadIdx.x < 16) atomicAdd(&g_bincnt[threadIdx.x], h[threadIdx.x]);
}

__global__ void k_offsets() {
    __shared__ int btot[16], binbase[16], bOffD[16];
    __shared__ int nbatch_s;
    int tid = threadIdx.x;
    if (tid == 0) {
        int off = 0;
        for (int b = 0; b < 16; ++b) {
            btot[b] = g_bincnt[b];
            binbase[b] = off;
            g_binoff[b] = off;
            off += btot[b];
        }
        int bo = 0;
        for (int b = 15; b >= 0; --b) { bOffD[b] = bo; bo += (btot[b] + 15) >> 4; }
        nbatch_s = bo;
        g_nbatch = bo;
    }
    __syncthreads();
    int nb = nbatch_s;
    for (int bi = tid; bi < nb; bi += blockDim.x) {
        int bin = 0;
#pragma unroll
        for (int b = 15; b >= 0; --b) {
            int nbb = (btot[b] + 15) >> 4;
            if (bi >= bOffD[b] && bi < bOffD[b] + nbb) { bin = b; break; }
        }
        int j = (bi - bOffD[bin]) * 16;
        g_batch_start[bi] = binbase[bin] + j;
        g_batch_info[bi]  = ((bin + 1) << 8) | min(16, btot[bin] - j);
    }
}

__global__ void k_scatter(const int* __restrict__ deg) {
    __shared__ int scnt[16], sbase[16], scur[16];
    int t = threadIdx.x;
    if (t < 16) { scnt[t] = 0; scur[t] = 0; }
    __syncthreads();
    int i = blockIdx.x * 512 + t;
    int d = -1;
    if (i < NNODES) { d = deg[i] - 1; atomicAdd(&scnt[d], 1); }
    __syncthreads();
    if (t < 16 && scnt[t] > 0) sbase[t] = atomicAdd(&g_binoff[t], scnt[t]);
    __syncthreads();
    if (i < NNODES) {
        int pos = sbase[d] + atomicAdd(&scur[d], 1);
        g_order[pos] = i;
    }
}

// ------- bf16 HMMA GEMM, K=128: direct-LDG A frags, fused uint4 B, bias-in-acc -------
__global__ __launch_bounds__(256, 2)
void hgemm(const __nv_bfloat16* __restrict__ A1, const __nv_bfloat16* __restrict__ A2,
           const uint4* __restrict__ W1, const uint4* __restrict__ W2,
           const float* __restrict__ bias, void* __restrict__ out,
           int M, int N, int relu, int obf16, int splits) {
    extern __shared__ char sm[];
    int Nc = N / splits;
    int NG = Nc >> 3;
    int NGfull = N >> 3;
    int nw4 = 4 * NG * 32;
    int sp = blockIdx.x & (splits - 1);
    int cbase = sp * Nc;
    int nCTA = gridDim.x >> (splits - 1);
    int npass = (A2 != nullptr) ? 2 : 1;
    uint4* wf1 = (uint4*)sm;
    uint4* wf2 = wf1 + nw4;
    float* bsm = (float*)(wf1 + (size_t)npass * nw4);

    int tid = threadIdx.x, wid = tid >> 5, lane = tid & 31;
    for (int i = tid; i < nw4; i += 256) {
        int t2 = i >> 5, li = i & 31;
        int kt = t2 / NG, gg = t2 - kt * NG;
        int src = (kt * NGfull + sp * NG + gg) * 32 + li;
        wf1[i] = W1[src];
        if (npass == 2) wf2[i] = W2[src];
    }
    if (bias) for (int i = tid; i < Nc; i += 256) bsm[i] = bias[cbase + i];
    __syncthreads();

    int rh = wid & 1, cc = wid >> 1;
    int gpw = NG >> 2;
    int r0 = lane >> 2, q = lane & 3;
    int nbat = (M + 31) >> 5;

    for (int bi = blockIdx.x >> (splits - 1); bi < nbat; bi += nCTA) {
        int gr0 = bi * 32 + rh * 16 + r0;
        int gr1 = gr0 + 8;
        int gr0c = min(gr0, M - 1), gr1c = min(gr1, M - 1);
        const __nv_bfloat16* Ar0 = A1 + (size_t)gr0c * 128 + q * 2;
        const __nv_bfloat16* Ar1 = A1 + (size_t)gr1c * 128 + q * 2;
        unsigned a1[8][4], a2[8][4];
#pragma unroll
        for (int kt = 0; kt < 8; ++kt) {
            a1[kt][0] = *(const unsigned*)(Ar0 + kt * 16);
            a1[kt][1] = *(const unsigned*)(Ar1 + kt * 16);
            a1[kt][2] = *(const unsigned*)(Ar0 + kt * 16 + 8);
            a1[kt][3] = *(const unsigned*)(Ar1 + kt * 16 + 8);
        }
        if (npass == 2) {
            const __nv_bfloat16* Br0 = A2 + (size_t)gr0c * 128 + q * 2;
            const __nv_bfloat16* Br1 = A2 + (size_t)gr1c * 128 + q * 2;
#pragma unroll
            for (int kt = 0; kt < 8; ++kt) {
                a2[kt][0] = *(const unsigned*)(Br0 + kt * 16);
                a2[kt][1] = *(const unsigned*)(Br1 + kt * 16);
                a2[kt][2] = *(const unsigned*)(Br0 + kt * 16 + 8);
                a2[kt][3] = *(const unsigned*)(Br1 + kt * 16 + 8);
            }
        }
        for (int g = 0; g < gpw; ++g) {
            int gg = cc * gpw + g;
            int c0l = gg * 8 + 2 * q;
            float b0 = 0.f, b1 = 0.f;
            if (bias) { b0 = bsm[c0l]; b1 = bsm[c0l + 1]; }
            float acc[4] = {0.f, 0.f, 0.f, 0.f};
            float acb[4] = {b0, b1, b0, b1};
#pragma unroll
            for (int kt = 0; kt < 4; ++kt) {
                uint4 b = wf1[(kt * NG + gg) * 32 + lane];
                mma16816(acc, a1[kt],     b.x, b.y);
                mma16816(acb, a1[kt + 4], b.z, b.w);
            }
            if (npass == 2) {
#pragma unroll
                for (int kt = 0; kt < 4; ++kt) {
                    uint4 b = wf2[(kt * NG + gg) * 32 + lane];
                    mma16816(acc, a2[kt],     b.x, b.y);
                    mma16816(acb, a2[kt + 4], b.z, b.w);
                }
            }
#pragma unroll
            for (int i = 0; i < 4; ++i) acc[i] += acb[i];
            float o0 = acc[0], o1 = acc[1], o2 = acc[2], o3 = acc[3];
            if (relu) {
                o0 = fmaxf(o0, 0.f); o1 = fmaxf(o1, 0.f);
                o2 = fmaxf(o2, 0.f); o3 = fmaxf(o3, 0.f);
            }
            int c0 = cbase + c0l;
            if (obf16) {
                unsigned w0 = bf16u(o0) | (bf16u(o1) << 16);
                unsigned w1 = bf16u(o2) | (bf16u(o3) << 16);
                if (gr0 < M) *(unsigned*)((__nv_bfloat16*)out + (size_t)gr0 * N + c0) = w0;
                if (gr1 < M) *(unsigned*)((__nv_bfloat16*)out + (size_t)gr1 * N + c0) = w1;
            } else {
                if (gr0 < M) *(float2*)((float*)out + (size_t)gr0 * N + c0) = make_float2(o0, o1);
                if (gr1 < M) *(float2*)((float*)out + (size_t)gr1 * N + c0) = make_float2(o2, o3);
            }
        }
    }
}

// ------- mma.sync LSTM: 4-warp groups, 4 groups/CTA, P+bias in acc init -------
#define LGROUPS 4
#define HSTRIDE 136
#define SM_WF    0
#define SM_BIAS  131072
#define SM_HSTG  133120
#define SM_NID   (SM_HSTG + 34816)
#define SM_USM   (SM_NID + 256)
#define SM_TOTAL (SM_USM + 4096)

__global__ __launch_bounds__(512, 1)
void lstm_mma(const int* __restrict__ nbr) {
    extern __shared__ char smr[];
    uint4*  wf  = (uint4*)(smr + SM_WF);
    float4* bsm = (float4*)(smr + SM_BIAS);
    __nv_bfloat16* hstg = (__nv_bfloat16*)(smr + SM_HSTG);
    int* nidA = (int*)(smr + SM_NID);
    int* usmA = (int*)(smr + SM_USM);

    int tid = threadIdx.x, wid = tid >> 5, lane = tid & 31;
    for (int i = tid; i < 256 * 32; i += 512) wf[i] = g_Wfrag4[i];
    if (tid < HID) bsm[tid] = g_biasF[tid];
    __syncthreads();

    int grp = wid >> 2, chunk = wid & 3;
    __nv_bfloat16* hs0 = hstg + grp * 2 * 16 * HSTRIDE;
    __nv_bfloat16* hs1 = hs0 + 16 * HSTRIDE;
    int* mynid = nidA + grp * 16;
    int* usm   = usmA + grp * 16 * MAXD;
    int r0 = lane >> 2, q = lane & 3;
    int barid = grp + 1;
    int nb = g_nbatch;
    const unsigned* PB = (const unsigned*)g_Pb;

    for (int b = blockIdx.x * LGROUPS + grp; b < nb; b += gridDim.x * LGROUPS) {
        asm volatile("bar.sync %0, %1;" :: "r"(barid), "r"(128) : "memory");
        int start = g_batch_start[b];
        int info  = g_batch_info[b];
        int dmax = info >> 8, cnt = info & 255;
        if (chunk == 0 && lane < 16) {
            int nid = g_order[start + min(lane, cnt - 1)];
            mynid[lane] = nid;
            const int4* src = (const int4*)(nbr + nid * MAXD);
            int4* dst = (int4*)(usm + lane * MAXD);
            dst[0] = src[0]; dst[1] = src[1]; dst[2] = src[2]; dst[3] = src[3];
        }
        asm volatile("bar.sync %0, %1;" :: "r"(barid), "r"(128) : "memory");

        float cst[16];
#pragma unroll
        for (int i = 0; i < 16; ++i) cst[i] = 0.f;

        unsigned pnl[16];
        {
            const unsigned* L = PB + (size_t)usm[r0 * MAXD] * 256;
#pragma unroll
            for (int nt = 0; nt < 16; ++nt) pnl[nt] = L[chunk * 64 + nt * 4 + q];
        }

        for (int t = 0; t < dmax; ++t) {
            asm volatile("bar.sync %0, %1;" :: "r"(barid), "r"(128) : "memory");
            const __nv_bfloat16* hsR = (t & 1) ? hs0 : hs1;
            __nv_bfloat16*       hsW = (t & 1) ? hs1 : hs0;

            unsigned a[8][4];
            if (t > 0) {
                const __nv_bfloat16* ab = hsR + (lane & 15) * HSTRIDE + ((lane >> 4) << 3);
#pragma unroll
                for (int kt = 0; kt < 8; ++kt) ldsm4(a[kt], ab + kt * 16);
            }
            unsigned pcl[16];
#pragma unroll
            for (int nt = 0; nt < 16; ++nt) pcl[nt] = pnl[nt];
            unsigned pch[16];
            {
                const unsigned* H = PB + (size_t)usm[(r0 + 8) * MAXD + t] * 256;
#pragma unroll
                for (int nt = 0; nt < 16; ++nt) pch[nt] = H[chunk * 64 + nt * 4 + q];
            }
            if (t + 1 < dmax) {
                const unsigned* L = PB + (size_t)usm[r0 * MAXD + t + 1] * 256;
#pragma unroll
                for (int nt = 0; nt < 16; ++nt) pnl[nt] = L[chunk * 64 + nt * 4 + q];
            }

            bool last = (t == dmax - 1);
#pragma unroll
            for (int p = 0; p < 8; ++p) {
                int J = chunk * 32 + p * 4 + q;
                float4 bs = bsm[J];
                // acc chains seeded with P (chain1) and bias (chain2)
                float aE[4]  = {blo(pcl[2 * p]),     bhi(pcl[2 * p]),
                                blo(pch[2 * p]),     bhi(pch[2 * p])};
                float aO[4]  = {blo(pcl[2 * p + 1]), bhi(pcl[2 * p + 1]),
                                blo(pch[2 * p + 1]), bhi(pch[2 * p + 1])};
                float aE2[4] = {bs.x, bs.y, bs.x, bs.y};
                float aO2[4] = {bs.z, bs.w, bs.z, bs.w};
                if (t > 0) {
#pragma unroll
                    for (int kt = 0; kt < 4; ++kt) {
                        uint4 b0 = wf[((kt << 5) | (chunk << 3) | p) * 32 + lane];
                        uint4 b1 = wf[(((kt + 4) << 5) | (chunk << 3) | p) * 32 + lane];
                        mma16816(aE,  a[kt],     b0.x, b0.y);
                        mma16816(aO,  a[kt],     b0.z, b0.w);
                        mma16816(aE2, a[kt + 4], b1.x, b1.y);
                        mma16816(aO2, a[kt + 4], b1.z, b1.w);
                    }
                }
#pragma unroll
                for (int i = 0; i < 4; ++i) { aE[i] += aE2[i]; aO[i] += aO2[i]; }
                {   // row r0
                    float cn = sigt(aE[1]) * cst[2 * p] + sigt(aE[0]) * tanhap(aO[0]);
                    cst[2 * p] = cn;
                    float h = sigt(aO[1]) * tanhap(cn);
                    if (!last) hsW[r0 * HSTRIDE + J] = __float2bfloat16(h);
                    else if (r0 < cnt) g_hTb[(size_t)mynid[r0] * HID + J] = __float2bfloat16(h);
                }
                {   // row r0+8
                    float cn = sigt(aE[3]) * cst[2 * p + 1] + sigt(aE[2]) * tanhap(aO[2]);
                    cst[2 * p + 1] = cn;
                    float h = sigt(aO[3]) * tanhap(cn);
                    if (!last) hsW[(r0 + 8) * HSTRIDE + J] = __float2bfloat16(h);
                    else if (r0 + 8 < cnt) g_hTb[(size_t)mynid[r0 + 8] * HID + J] = __float2bfloat16(h);
                }
            }
        }
    }
}

// ---------------- GraphConv aggregate (bf16 in/out) ----------------
__global__ void agg_kernel(const int* __restrict__ nbr, const int* __restrict__ deg) {
    int wid  = (blockIdx.x * blockDim.x + threadIdx.x) >> 5;
    int lane = threadIdx.x & 31;
    if (wid >= NNODES) return;
    int d = deg[wid];
    const int* nb = nbr + wid * MAXD;
    float a0 = 0.f, a1 = 0.f, a2 = 0.f, a3 = 0.f;
    for (int t = 0; t < d; ++t) {
        int u = nb[t];
        float nu = rsqrtf((float)max(deg[u], 1));
        uint2 v = *(const uint2*)(g_h1b + (size_t)u * 128 + lane * 4);
        a0 = fmaf(blo(v.x), nu, a0); a1 = fmaf(bhi(v.x), nu, a1);
        a2 = fmaf(blo(v.y), nu, a2); a3 = fmaf(bhi(v.y), nu, a3);
    }
    float nn = rsqrtf((float)max(d, 1));
    uint2 o;
    o.x = bf16u(a0 * nn) | (bf16u(a1 * nn) << 16);
    o.y = bf16u(a2 * nn) | (bf16u(a3 * nn) << 16);
    *(uint2*)(g_aggB + (size_t)wid * 128 + lane * 4) = o;
}

// ---------------- GRU activation ----------------
__global__ void gruact(const float* __restrict__ bih, const float* __restrict__ bhh) {
    int i = blockIdx.x * blockDim.x + threadIdx.x;
    if (i >= NNODES * GRUH) return;
    int n = i >> 5, l = i & 31;
    const float* g = g_gh + (size_t)n * 96;
    float xr = g[l]      + bih[l];
    float xz = g[32 + l] + bih[32 + l];
    float xn = g[64 + l] + bih[64 + l];
    float r   = sigf(xr + bhh[l]);
    float z   = sigf(xz + bhh[32 + l]);
    float nst = tanh_(xn + r * bhh[64 + l]);
    g_o32[i] = (1.f - z) * nst;
}

// ---------------- mean pool (two-pass) + classifier ----------------
__global__ void pool1(const int* __restrict__ gid) {
    __shared__ float s[8][32];
    __shared__ int   scnt[8];
    int g = blockIdx.x, part = blockIdx.y;
    int tid = threadIdx.x, lane = tid & 31, slot = tid >> 5;
    int base = part * (NNODES / 4), end = base + NNODES / 4;
    float acc = 0.f;
    int cnt = 0;
    for (int i = base + slot; i < end; i += 8) {
        if (gid[i] == g) {
            acc += g_o32[(size_t)i * 32 + lane];
            cnt++;
        }
    }
    s[slot][lane] = acc;
    if (lane == 0) scnt[slot] = cnt;
    __syncthreads();
    if (tid < 32) {
        float sum = 0.f; int tot = 0;
#pragma unroll
        for (int j = 0; j < 8; ++j) { sum += s[j][tid]; tot += scnt[j]; }
        g_pp[g][part][tid] = sum;
        if (tid == 0) g_pc[g][part] = tot;
    }
}

__global__ void pool2(const float* __restrict__ Wc, const float* __restrict__ bc,
                      float* __restrict__ out) {
    __shared__ float hg[32];
    int g = blockIdx.x, tid = threadIdx.x;
    float sum = g_pp[g][0][tid] + g_pp[g][1][tid] + g_pp[g][2][tid] + g_pp[g][3][tid];
    int tot = g_pc[g][0] + g_pc[g][1] + g_pc[g][2] + g_pc[g][3];
    hg[tid] = sum / (float)tot;
    __syncwarp();
    if (tid < NCLS) {
        float o = bc[tid];
#pragma unroll
        for (int k = 0; k < 32; ++k) o = fmaf(hg[k], Wc[k * NCLS + tid], o);
        out[g * NCLS + tid] = o;
    }
}

// ---------------- launch ----------------
extern "C" void kernel_launch(void* const* d_in, const int* in_sizes, int n_in,
                              void* d_out, int out_size) {
    const float* feature = (const float*)d_in[0];
    const int*   nbr     = (const int*)  d_in[1];
    const int*   deg     = (const int*)  d_in[2];
    const int*   gid     = (const int*)  d_in[3];
    const float* lWih    = (const float*)d_in[4];
    const float* lWhh    = (const float*)d_in[5];
    const float* lbih    = (const float*)d_in[6];
    const float* lbhh    = (const float*)d_in[7];
    const float* Wself   = (const float*)d_in[8];
    const float* Wneigh  = (const float*)d_in[9];
    const float* bsage   = (const float*)d_in[10];
    const float* Wgc     = (const float*)d_in[11];
    const float* bgc     = (const float*)d_in[12];
    const float* Wgru    = (const float*)d_in[13];
    const float* bihg    = (const float*)d_in[14];
    const float* bhhg    = (const float*)d_in[15];
    const float* Wcls    = (const float*)d_in[16];
    const float* bcls    = (const float*)d_in[17];
    float* out = (float*)d_out;

    // smem: weights only now
    const int smP = 4096 * 16 + 1024 + 256;          // split NG=32: 64KB + bias
    const int smS = 2 * 2048 * 16 + 512 + 256;       // 2-pass N=128: 64KB
    const int smG = 2048 * 16 + 512 + 256;           // 32KB
    const int smR = 1536 * 16 + 512 + 256;           // 24KB

    cudaFuncSetAttribute(hgemm, cudaFuncAttributeMaxDynamicSharedMemorySize, 70000);
    cudaFuncSetAttribute(lstm_mma, cudaFuncAttributeMaxDynamicSharedMemorySize, SM_TOTAL);

    void *pPb, *pFeatB, *pHtb, *pH1b, *pAggB, *pH2b, *pGh;
    void *pWfP, *pWfSelf, *pWfNeigh, *pWfGc, *pWfGru;
    cudaGetSymbolAddress(&pPb,     g_Pb);
    cudaGetSymbolAddress(&pFeatB,  g_featB);
    cudaGetSymbolAddress(&pHtb,    g_hTb);
    cudaGetSymbolAddress(&pH1b,    g_h1b);
    cudaGetSymbolAddress(&pAggB,   g_aggB);
    cudaGetSymbolAddress(&pH2b,    g_h2b);
    cudaGetSymbolAddress(&pGh,     g_gh);
    cudaGetSymbolAddress(&pWfP,    g_WfP4);
    cudaGetSymbolAddress(&pWfSelf, g_WfSelf4);
    cudaGetSymbolAddress(&pWfNeigh,g_WfNeigh4);
    cudaGetSymbolAddress(&pWfGc,   g_WfGc4);
    cudaGetSymbolAddress(&pWfGru,  g_WfGru4);

    prep_kernel<<<256, 256>>>(lWih, lWhh, lbih, lbhh, Wself, Wneigh, Wgc, Wgru);
    k_hist_f2b<<<148, 512>>>(deg, feature, (__nv_bfloat16*)pFeatB);
    // P = featB @ WihT(perm) -> bf16 [N,512], split x2
    hgemm<<<304, 256, smP>>>((const __nv_bfloat16*)pFeatB, nullptr,
                             (const uint4*)pWfP, nullptr, nullptr, pPb,
                             NNODES, 512, 0, 1, 2);
    k_offsets<<<1, 512>>>();
    k_scatter<<<98, 512>>>(deg);
    lstm_mma<<<152, 512, SM_TOTAL>>>(nbr);
    // h1 = relu(featB@Wself + hTb@Wneigh + b_sage) -> bf16
    hgemm<<<304, 256, smS>>>((const __nv_bfloat16*)pFeatB, (const __nv_bfloat16*)pHtb,
                             (const uint4*)pWfSelf, (const uint4*)pWfNeigh, bsage, pH1b,
                             NNODES, 128, 1, 1, 1);
    agg_kernel<<<(NNODES * 32 + 255) / 256, 256>>>(nbr, deg);
    // h2 = relu(aggB @ Wgc + b_gc) -> bf16
    hgemm<<<304, 256, smG>>>((const __nv_bfloat16*)pAggB, nullptr,
                             (const uint4*)pWfGc, nullptr, bgc, pH2b,
                             NNODES, 128, 1, 1, 1);
    // gh = h2b @ WgruT -> f32 [N,96]
    hgemm<<<304, 256, smR>>>((const __nv_bfloat16*)pH2b, nullptr,
                             (const uint4*)pWfGru, nullptr, nullptr, pGh,
                             NNODES, 96, 0, 0, 1);
    gruact<<<(NNODES * GRUH + 255) / 256, 256>>>(bihg, bhhg);
    pool1<<<dim3(NGRAPH, 4), 256>>>(gid);
    pool2<<<NGRAPH, 32>>>(Wcls, bcls, out);
}

// round 16
// speedup vs baseline: 1.1243x; 1.1243x over previous
#include <cuda_runtime.h>
#include <cuda_bf16.h>
#include <cstdint>

#define NNODES 50000
#define HID    128
#define MAXD   16
#define NGRAPH 50
#define NCLS   10
#define GRUH   32
#define MAXB   3400

// ---------------- scratch ----------------
__device__ __nv_bfloat16 g_Pb [(size_t)NNODES * 512];
__device__ __nv_bfloat16 g_featB[(size_t)NNODES * HID];
__device__ __nv_bfloat16 g_hTb [(size_t)NNODES * HID];
__device__ __nv_bfloat16 g_h1b [(size_t)NNODES * HID];
__device__ __nv_bfloat16 g_aggB[(size_t)NNODES * HID];
__device__ __nv_bfloat16 g_h2b [(size_t)NNODES * HID];
__device__ float g_gh [(size_t)NNODES * 96];
__device__ float g_o32[(size_t)NNODES * GRUH];
// fused (kt, kt+4) weight fragments: uint4 = {frag(kt).xy, frag(kt+4).xy}
__device__ uint4 g_WfP4   [8192];   // N=512 (64 groups), kt-major
__device__ uint4 g_WfSelf4[2048];   // N=128
__device__ uint4 g_WfNeigh4[2048];
__device__ uint4 g_WfGc4  [2048];
__device__ uint4 g_WfGru4 [1536];   // N=96
__device__ uint4 g_Wfrag4[256 * 32];         // lstm Whh fragments, E/O fused
__device__ float4 g_biasF[HID];              // (bi,bf,bg,bo)
__device__ float g_pp[NGRAPH][4][32];
__device__ int   g_pc[NGRAPH][4];
// degree bucketing
__device__ int g_order[NNODES];
__device__ int g_bincnt[16];
__device__ int g_binoff[16];
__device__ int g_batch_start[MAXB];
__device__ int g_batch_info[MAXB];
__device__ int g_nbatch;

// ---------------- helpers ----------------
__device__ __forceinline__ float sigf(float x) {
    x = fminf(fmaxf(x, -30.f), 30.f);
    return __fdividef(1.f, 1.f + __expf(-x));
}
__device__ __forceinline__ float tanh_(float x) {
    x = fminf(fmaxf(x, -15.f), 15.f);
    float e = __expf(-2.f * x);
    return __fdividef(1.f - e, 1.f + e);
}
__device__ __forceinline__ float tanhap(float x) {
    float y; asm("tanh.approx.f32 %0, %1;" : "=f"(y) : "f"(x)); return y;
}
__device__ __forceinline__ float sigt(float x) { return fmaf(tanhap(x * 0.5f), 0.5f, 0.5f); }
__device__ __forceinline__ unsigned bf16u(float x) {
    __nv_bfloat16 b = __float2bfloat16(x);
    return (unsigned)*reinterpret_cast<unsigned short*>(&b);
}
__device__ __forceinline__ float blo(unsigned v) { return __uint_as_float(v << 16); }
__device__ __forceinline__ float bhi(unsigned v) { return __uint_as_float(v & 0xFFFF0000u); }

__host__ __device__ __forceinline__ int phys2row(int p) {
    int pb = p >> 4, rem = p & 15;
    int gamma, aa;
    if (rem < 8) { aa = rem >> 1; gamma = (rem & 1) ? 1 : 0; }
    else         { aa = (rem - 8) >> 1; gamma = (rem & 1) ? 3 : 2; }
    return gamma * HID + pb * 4 + aa;
}

__device__ __forceinline__ void mma16816(float* d, const unsigned* a, unsigned b0, unsigned b1) {
    asm volatile(
        "mma.sync.aligned.m16n8k16.row.col.f32.bf16.bf16.f32 "
        "{%0,%1,%2,%3}, {%4,%5,%6,%7}, {%8,%9}, {%0,%1,%2,%3};"
        : "+f"(d[0]), "+f"(d[1]), "+f"(d[2]), "+f"(d[3])
        : "r"(a[0]), "r"(a[1]), "r"(a[2]), "r"(a[3]), "r"(b0), "r"(b1));
}

__device__ __forceinline__ void ldsm4(unsigned* r, const void* p) {
    unsigned addr = (unsigned)__cvta_generic_to_shared(p);
    asm volatile("ldmatrix.sync.aligned.m8n8.x4.shared.b16 {%0,%1,%2,%3}, [%4];"
                 : "=r"(r[0]), "=r"(r[1]), "=r"(r[2]), "=r"(r[3]) : "r"(addr));
}

// ---------------- prep: all weight packing (+ bincnt reset) ----------------
__global__ void prep_kernel(const float* __restrict__ Wih,
                            const float* __restrict__ Whh,
                            const float* __restrict__ bih,
                            const float* __restrict__ bhh,
                            const float* __restrict__ Wself,
                            const float* __restrict__ Wneigh,
                            const float* __restrict__ Wgc,
                            const float* __restrict__ Wgru) {
    int idx = blockIdx.x * blockDim.x + threadIdx.x;
    int l = idx & 31, t = idx >> 5;
    if (idx < 16) g_bincnt[idx] = 0;
    if (idx < 8192) {                  // P fused: kt 0..3 paired with kt+4
        int kt = t >> 6, gg = t & 63;
        int n = gg * 8 + (l >> 2);
        int r = phys2row(n) * HID;
        int ka = kt * 16 + (l & 3) * 2;
        int kb = ka + 64;
        uint4 v;
        v.x = bf16u(Wih[r + ka])     | (bf16u(Wih[r + ka + 1]) << 16);
        v.y = bf16u(Wih[r + ka + 8]) | (bf16u(Wih[r + ka + 9]) << 16);
        v.z = bf16u(Wih[r + kb])     | (bf16u(Wih[r + kb + 1]) << 16);
        v.w = bf16u(Wih[r + kb + 8]) | (bf16u(Wih[r + kb + 9]) << 16);
        g_WfP4[idx] = v;
    }
    if (idx < 2048) {                  // Self/Neigh/Gc fused (K-major source)
        int kt = t >> 4, gg = t & 15;
        int n = gg * 8 + (l >> 2);
        int ka = kt * 16 + (l & 3) * 2;
        int kb = ka + 64;
        uint4 v;
        v.x = bf16u(Wself[ka * HID + n])       | (bf16u(Wself[(ka + 1) * HID + n]) << 16);
        v.y = bf16u(Wself[(ka + 8) * HID + n]) | (bf16u(Wself[(ka + 9) * HID + n]) << 16);
        v.z = bf16u(Wself[kb * HID + n])       | (bf16u(Wself[(kb + 1) * HID + n]) << 16);
        v.w = bf16u(Wself[(kb + 8) * HID + n]) | (bf16u(Wself[(kb + 9) * HID + n]) << 16);
        g_WfSelf4[idx] = v;
        v.x = bf16u(Wneigh[ka * HID + n])       | (bf16u(Wneigh[(ka + 1) * HID + n]) << 16);
        v.y = bf16u(Wneigh[(ka + 8) * HID + n]) | (bf16u(Wneigh[(ka + 9) * HID + n]) << 16);
        v.z = bf16u(Wneigh[kb * HID + n])       | (bf16u(Wneigh[(kb + 1) * HID + n]) << 16);
        v.w = bf16u(Wneigh[(kb + 8) * HID + n]) | (bf16u(Wneigh[(kb + 9) * HID + n]) << 16);
        g_WfNeigh4[idx] = v;
        v.x = bf16u(Wgc[ka * HID + n])       | (bf16u(Wgc[(ka + 1) * HID + n]) << 16);
        v.y = bf16u(Wgc[(ka + 8) * HID + n]) | (bf16u(Wgc[(ka + 9) * HID + n]) << 16);
        v.z = bf16u(Wgc[kb * HID + n])       | (bf16u(Wgc[(kb + 1) * HID + n]) << 16);
        v.w = bf16u(Wgc[(kb + 8) * HID + n]) | (bf16u(Wgc[(kb + 9) * HID + n]) << 16);
        g_WfGc4[idx] = v;
    }
    if (idx < 1536) {                  // GRU fused (row-major source)
        int kt = t / 12, gg = t % 12;
        int n = gg * 8 + (l >> 2);
        int ka = kt * 16 + (l & 3) * 2;
        int kb = ka + 64;
        const float* wr = Wgru + (size_t)n * HID;
        uint4 v;
        v.x = bf16u(wr[ka])     | (bf16u(wr[ka + 1]) << 16);
        v.y = bf16u(wr[ka + 8]) | (bf16u(wr[ka + 9]) << 16);
        v.z = bf16u(wr[kb])     | (bf16u(wr[kb + 1]) << 16);
        v.w = bf16u(wr[kb + 8]) | (bf16u(wr[kb + 9]) << 16);
        g_WfGru4[idx] = v;
    }
    if (idx < 512 * 32) {
        int t_id = t, lane = l;
        int kt = t_id >> 6, ntg = t_id & 63;
        int p = ntg * 8 + (lane >> 2);
        int wrow = phys2row(p);
        int k0 = kt * 16 + (lane & 3) * 2;
        const float* wr = Whh + (size_t)wrow * HID;
        uint2 v;
        v.x = bf16u(wr[k0])     | (bf16u(wr[k0 + 1]) << 16);
        v.y = bf16u(wr[k0 + 8]) | (bf16u(wr[k0 + 9]) << 16);
        int chunk = ntg >> 4, nt = ntg & 15;
        int pp = nt >> 1, isO = nt & 1;
        int dst = (((kt << 5) | (chunk << 3) | pp) * 32 + lane) * 2 + isO;
        ((uint2*)g_Wfrag4)[dst] = v;
    }
    if (idx < HID) {
        g_biasF[idx] = make_float4(bih[idx] + bhh[idx],
                                   bih[HID + idx] + bhh[HID + idx],
                                   bih[2 * HID + idx] + bhh[2 * HID + idx],
                                   bih[3 * HID + idx] + bhh[3 * HID + idx]);
    }
}

// ------- hist + feature->bf16 fused -------
__global__ void k_hist_f2b(const int* __restrict__ deg,
                           const float* __restrict__ src,
                           __nv_bfloat16* __restrict__ dst) {
    __shared__ int h[16];
    if (threadIdx.x < 16) h[threadIdx.x] = 0;
    __syncthreads();
    int stride = gridDim.x * blockDim.x;
    for (int i = blockIdx.x * blockDim.x + threadIdx.x; i < NNODES; i += stride)
        atomicAdd(&h[deg[i] - 1], 1);
    const int n4 = NNODES * HID / 4;
    for (int i = blockIdx.x * blockDim.x + threadIdx.x; i < n4; i += stride) {
        float4 v = ((const float4*)src)[i];
        uint2 o;
        o.x = bf16u(v.x) | (bf16u(v.y) << 16);
        o.y = bf16u(v.z) | (bf16u(v.w) << 16);
        ((uint2*)dst)[i] = o;
    }
    __syncthreads();
    if (threadIdx.x < 16) atomicAdd(&g_bincnt[threadIdx.x], h[threadIdx.x]);
}

__global__ void k_offsets() {
    __shared__ int btot[16], binbase[16], bOffD[16];
    __shared__ int nbatch_s;
    int tid = threadIdx.x;
    if (tid == 0) {
        int off = 0;
        for (int b = 0; b < 16; ++b) {
            btot[b] = g_bincnt[b];
            binbase[b] = off;
            g_binoff[b] = off;
            off += btot[b];
        }
        int bo = 0;
        for (int b = 15; b >= 0; --b) { bOffD[b] = bo; bo += (btot[b] + 15) >> 4; }
        nbatch_s = bo;
        g_nbatch = bo;
    }
    __syncthreads();
    int nb = nbatch_s;
    for (int bi = tid; bi < nb; bi += blockDim.x) {
        int bin = 0;
#pragma unroll
        for (int b = 15; b >= 0; --b) {
            int nbb = (btot[b] + 15) >> 4;
            if (bi >= bOffD[b] && bi < bOffD[b] + nbb) { bin = b; break; }
        }
        int j = (bi - bOffD[bin]) * 16;
        g_batch_start[bi] = binbase[bin] + j;
        g_batch_info[bi]  = ((bin + 1) << 8) | min(16, btot[bin] - j);
    }
}

__global__ void k_scatter(const int* __restrict__ deg) {
    __shared__ int scnt[16], sbase[16], scur[16];
    int t = threadIdx.x;
    if (t < 16) { scnt[t] = 0; scur[t] = 0; }
    __syncthreads();
    int i = blockIdx.x * 512 + t;
    int d = -1;
    if (i < NNODES) { d = deg[i] - 1; atomicAdd(&scnt[d], 1); }
    __syncthreads();
    if (t < 16 && scnt[t] > 0) sbase[t] = atomicAdd(&g_binoff[t], scnt[t]);
    __syncthreads();
    if (i < NNODES) {
        int pos = sbase[d] + atomicAdd(&scur[d], 1);
        g_order[pos] = i;
    }
}

// ------- bf16 HMMA GEMM (R13 config): smem-staged A + ldmatrix, fused uint4 B -------
#define AS 136

__global__ __launch_bounds__(256, 2)
void hgemm(const __nv_bfloat16* __restrict__ A1, const __nv_bfloat16* __restrict__ A2,
           const uint4* __restrict__ W1, const uint4* __restrict__ W2,
           const float* __restrict__ bias, void* __restrict__ out,
           int M, int N, int relu, int obf16, int splits) {
    extern __shared__ char sm[];
    int Nc = N / splits;
    int NG = Nc >> 3;
    int NGfull = N >> 3;
    int nw4 = 4 * NG * 32;
    int sp = blockIdx.x & (splits - 1);
    int cbase = sp * Nc;
    int nCTA = gridDim.x >> (splits - 1);
    int npass = (A2 != nullptr) ? 2 : 1;
    uint4* wf1 = (uint4*)sm;
    uint4* wf2 = wf1 + nw4;
    unsigned short* ast = (unsigned short*)(wf1 + (size_t)npass * nw4);
    float* bsm = (float*)(ast + npass * 32 * AS);

    int tid = threadIdx.x, wid = tid >> 5, lane = tid & 31;
    {
        for (int i = tid; i < nw4; i += 256) {
            int t2 = i >> 5, li = i & 31;
            int kt = t2 / NG, gg = t2 - kt * NG;
            int src = (kt * NGfull + sp * NG + gg) * 32 + li;
            wf1[i] = W1[src];
            if (npass == 2) wf2[i] = W2[src];
        }
    }
    if (bias) for (int i = tid; i < Nc; i += 256) bsm[i] = bias[cbase + i];

    int rh = wid & 1, cc = wid >> 1;
    int gpw = NG >> 2;
    int r0 = lane >> 2, q = lane & 3;
    int nbat = (M + 31) >> 5;
    int lrow = tid >> 3, lch = tid & 7;

    uint4 pf[2][2];
    int bi = blockIdx.x >> (splits - 1);
    if (bi < nbat) {
        int gr = min(bi * 32 + lrow, M - 1);
        const uint4* s = (const uint4*)(A1 + (size_t)gr * 128 + lch * 16);
        pf[0][0] = s[0]; pf[0][1] = s[1];
        if (npass == 2) {
            const uint4* s2 = (const uint4*)(A2 + (size_t)gr * 128 + lch * 16);
            pf[1][0] = s2[0]; pf[1][1] = s2[1];
        }
    }
    __syncthreads();

    for (; bi < nbat; bi += nCTA) {
        {
            uint4* d = (uint4*)(ast + lrow * AS + lch * 16);
            d[0] = pf[0][0]; d[1] = pf[0][1];
            if (npass == 2) {
                uint4* d2 = (uint4*)(ast + 32 * AS + lrow * AS + lch * 16);
                d2[0] = pf[1][0]; d2[1] = pf[1][1];
            }
        }
        __syncthreads();
        int bn = bi + nCTA;
        if (bn < nbat) {
            int gr = min(bn * 32 + lrow, M - 1);
            const uint4* s = (const uint4*)(A1 + (size_t)gr * 128 + lch * 16);
            pf[0][0] = s[0]; pf[0][1] = s[1];
            if (npass == 2) {
                const uint4* s2 = (const uint4*)(A2 + (size_t)gr * 128 + lch * 16);
                pf[1][0] = s2[0]; pf[1][1] = s2[1];
            }
        }
        unsigned a1[8][4], a2[8][4];
        {
            const unsigned short* abase = ast + (rh * 16 + (lane & 15)) * AS + ((lane >> 4) << 3);
#pragma unroll
            for (int kt = 0; kt < 8; ++kt) ldsm4(a1[kt], abase + kt * 16);
            if (npass == 2) {
                const unsigned short* ab2 = abase + 32 * AS;
#pragma unroll
                for (int kt = 0; kt < 8; ++kt) ldsm4(a2[kt], ab2 + kt * 16);
            }
        }
        int gr0b = bi * 32 + rh * 16 + r0;
        for (int g = 0; g < gpw; ++g) {
            int gg = cc * gpw + g;
            float acc[4] = {0.f, 0.f, 0.f, 0.f};
            float acb[4] = {0.f, 0.f, 0.f, 0.f};
#pragma unroll
            for (int kt = 0; kt < 4; ++kt) {
                uint4 b = wf1[(kt * NG + gg) * 32 + lane];
                mma16816(acc, a1[kt],     b.x, b.y);
                mma16816(acb, a1[kt + 4], b.z, b.w);
            }
            if (npass == 2) {
#pragma unroll
                for (int kt = 0; kt < 4; ++kt) {
                    uint4 b = wf2[(kt * NG + gg) * 32 + lane];
                    mma16816(acc, a2[kt],     b.x, b.y);
                    mma16816(acb, a2[kt + 4], b.z, b.w);
                }
            }
#pragma unroll
            for (int i = 0; i < 4; ++i) acc[i] += acb[i];
            int c0l = gg * 8 + 2 * q;
            int c0 = cbase + c0l;
            float b0 = 0.f, b1 = 0.f;
            if (bias) { b0 = bsm[c0l]; b1 = bsm[c0l + 1]; }
            float o0 = acc[0] + b0, o1 = acc[1] + b1, o2 = acc[2] + b0, o3 = acc[3] + b1;
            if (relu) {
                o0 = fmaxf(o0, 0.f); o1 = fmaxf(o1, 0.f);
                o2 = fmaxf(o2, 0.f); o3 = fmaxf(o3, 0.f);
            }
            int gr1 = gr0b + 8;
            if (obf16) {
                unsigned w0 = bf16u(o0) | (bf16u(o1) << 16);
                unsigned w1 = bf16u(o2) | (bf16u(o3) << 16);
                if (gr0b < M) *(unsigned*)((__nv_bfloat16*)out + (size_t)gr0b * N + c0) = w0;
                if (gr1  < M) *(unsigned*)((__nv_bfloat16*)out + (size_t)gr1  * N + c0) = w1;
            } else {
                if (gr0b < M) *(float2*)((float*)out + (size_t)gr0b * N + c0) = make_float2(o0, o1);
                if (gr1  < M) *(float2*)((float*)out + (size_t)gr1  * N + c0) = make_float2(o2, o3);
            }
        }
        __syncthreads();
    }
}

// ------- mma.sync LSTM: 4-warp groups, 4 groups/CTA, P+bias in acc init -------
#define LGROUPS 4
#define HSTRIDE 136
#define SM_WF    0
#define SM_BIAS  131072
#define SM_HSTG  133120
#define SM_NID   (SM_HSTG + 34816)
#define SM_USM   (SM_NID + 256)
#define SM_TOTAL (SM_USM + 4096)

__global__ __launch_bounds__(512, 1)
void lstm_mma(const int* __restrict__ nbr) {
    extern __shared__ char smr[];
    uint4*  wf  = (uint4*)(smr + SM_WF);
    float4* bsm = (float4*)(smr + SM_BIAS);
    __nv_bfloat16* hstg = (__nv_bfloat16*)(smr + SM_HSTG);
    int* nidA = (int*)(smr + SM_NID);
    int* usmA = (int*)(smr + SM_USM);

    int tid = threadIdx.x, wid = tid >> 5, lane = tid & 31;
    for (int i = tid; i < 256 * 32; i += 512) wf[i] = g_Wfrag4[i];
    if (tid < HID) bsm[tid] = g_biasF[tid];
    __syncthreads();

    int grp = wid >> 2, chunk = wid & 3;
    __nv_bfloat16* hs0 = hstg + grp * 2 * 16 * HSTRIDE;
    __nv_bfloat16* hs1 = hs0 + 16 * HSTRIDE;
    int* mynid = nidA + grp * 16;
    int* usm   = usmA + grp * 16 * MAXD;
    int r0 = lane >> 2, q = lane & 3;
    int barid = grp + 1;
    int nb = g_nbatch;
    const unsigned* PB = (const unsigned*)g_Pb;

    for (int b = blockIdx.x * LGROUPS + grp; b < nb; b += gridDim.x * LGROUPS) {
        asm volatile("bar.sync %0, %1;" :: "r"(barid), "r"(128) : "memory");
        int start = g_batch_start[b];
        int info  = g_batch_info[b];
        int dmax = info >> 8, cnt = info & 255;
        if (chunk == 0 && lane < 16) {
            int nid = g_order[start + min(lane, cnt - 1)];
            mynid[lane] = nid;
            const int4* src = (const int4*)(nbr + nid * MAXD);
            int4* dst = (int4*)(usm + lane * MAXD);
            dst[0] = src[0]; dst[1] = src[1]; dst[2] = src[2]; dst[3] = src[3];
        }
        asm volatile("bar.sync %0, %1;" :: "r"(barid), "r"(128) : "memory");

        float cst[16];
#pragma unroll
        for (int i = 0; i < 16; ++i) cst[i] = 0.f;

        unsigned pnl[16];
        {
            const unsigned* L = PB + (size_t)usm[r0 * MAXD] * 256;
#pragma unroll
            for (int nt = 0; nt < 16; ++nt) pnl[nt] = L[chunk * 64 + nt * 4 + q];
        }

        for (int t = 0; t < dmax; ++t) {
            asm volatile("bar.sync %0, %1;" :: "r"(barid), "r"(128) : "memory");
            const __nv_bfloat16* hsR = (t & 1) ? hs0 : hs1;
            __nv_bfloat16*       hsW = (t & 1) ? hs1 : hs0;

            unsigned a[8][4];
            if (t > 0) {
                const __nv_bfloat16* ab = hsR + (lane & 15) * HSTRIDE + ((lane >> 4) << 3);
#pragma unroll
                for (int kt = 0; kt < 8; ++kt) ldsm4(a[kt], ab + kt * 16);
            }
            unsigned pcl[16];
#pragma unroll
            for (int nt = 0; nt < 16; ++nt) pcl[nt] = pnl[nt];
            unsigned pch[16];
            {
                const unsigned* H = PB + (size_t)usm[(r0 + 8) * MAXD + t] * 256;
#pragma unroll
                for (int nt = 0; nt < 16; ++nt) pch[nt] = H[chunk * 64 + nt * 4 + q];
            }
            if (t + 1 < dmax) {
                const unsigned* L = PB + (size_t)usm[r0 * MAXD + t + 1] * 256;
#pragma unroll
                for (int nt = 0; nt < 16; ++nt) pnl[nt] = L[chunk * 64 + nt * 4 + q];
            }

            bool last = (t == dmax - 1);
#pragma unroll
            for (int p = 0; p < 8; ++p) {
                int J = chunk * 32 + p * 4 + q;
                float4 bs = bsm[J];
                float aE[4]  = {blo(pcl[2 * p]),     bhi(pcl[2 * p]),
                                blo(pch[2 * p]),     bhi(pch[2 * p])};
                float aO[4]  = {blo(pcl[2 * p + 1]), bhi(pcl[2 * p + 1]),
                                blo(pch[2 * p + 1]), bhi(pch[2 * p + 1])};
                float aE2[4] = {bs.x, bs.y, bs.x, bs.y};
                float aO2[4] = {bs.z, bs.w, bs.z, bs.w};
                if (t > 0) {
#pragma unroll
                    for (int kt = 0; kt < 4; ++kt) {
                        uint4 b0 = wf[((kt << 5) | (chunk << 3) | p) * 32 + lane];
                        uint4 b1 = wf[(((kt + 4) << 5) | (chunk << 3) | p) * 32 + lane];
                        mma16816(aE,  a[kt],     b0.x, b0.y);
                        mma16816(aO,  a[kt],     b0.z, b0.w);
                        mma16816(aE2, a[kt + 4], b1.x, b1.y);
                        mma16816(aO2, a[kt + 4], b1.z, b1.w);
                    }
                }
#pragma unroll
                for (int i = 0; i < 4; ++i) { aE[i] += aE2[i]; aO[i] += aO2[i]; }
                {   // row r0
                    float cn = sigt(aE[1]) * cst[2 * p] + sigt(aE[0]) * tanhap(aO[0]);
                    cst[2 * p] = cn;
                    float h = sigt(aO[1]) * tanhap(cn);
                    if (!last) hsW[r0 * HSTRIDE + J] = __float2bfloat16(h);
                    else if (r0 < cnt) g_hTb[(size_t)mynid[r0] * HID + J] = __float2bfloat16(h);
                }
                {   // row r0+8
                    float cn = sigt(aE[3]) * cst[2 * p + 1] + sigt(aE[2]) * tanhap(aO[2]);
                    cst[2 * p + 1] = cn;
                    float h = sigt(aO[3]) * tanhap(cn);
                    if (!last) hsW[(r0 + 8) * HSTRIDE + J] = __float2bfloat16(h);
                    else if (r0 + 8 < cnt) g_hTb[(size_t)mynid[r0 + 8] * HID + J] = __float2bfloat16(h);
                }
            }
        }
    }
}

// ---------------- GraphConv aggregate (bf16 in/out) ----------------
__global__ void agg_kernel(const int* __restrict__ nbr, const int* __restrict__ deg) {
    int wid  = (blockIdx.x * blockDim.x + threadIdx.x) >> 5;
    int lane = threadIdx.x & 31;
    if (wid >= NNODES) return;
    int d = deg[wid];
    const int* nb = nbr + wid * MAXD;
    float a0 = 0.f, a1 = 0.f, a2 = 0.f, a3 = 0.f;
    for (int t = 0; t < d; ++t) {
        int u = nb[t];
        float nu = rsqrtf((float)max(deg[u], 1));
        uint2 v = *(const uint2*)(g_h1b + (size_t)u * 128 + lane * 4);
        a0 = fmaf(blo(v.x), nu, a0); a1 = fmaf(bhi(v.x), nu, a1);
        a2 = fmaf(blo(v.y), nu, a2); a3 = fmaf(bhi(v.y), nu, a3);
    }
    float nn = rsqrtf((float)max(d, 1));
    uint2 o;
    o.x = bf16u(a0 * nn) | (bf16u(a1 * nn) << 16);
    o.y = bf16u(a2 * nn) | (bf16u(a3 * nn) << 16);
    *(uint2*)(g_aggB + (size_t)wid * 128 + lane * 4) = o;
}

// ---------------- GRU activation ----------------
__global__ void gruact(const float* __restrict__ bih, const float* __restrict__ bhh) {
    int i = blockIdx.x * blockDim.x + threadIdx.x;
    if (i >= NNODES * GRUH) return;
    int n = i >> 5, l = i & 31;
    const float* g = g_gh + (size_t)n * 96;
    float xr = g[l]      + bih[l];
    float xz = g[32 + l] + bih[32 + l];
    float xn = g[64 + l] + bih[64 + l];
    float r   = sigf(xr + bhh[l]);
    float z   = sigf(xz + bhh[32 + l]);
    float nst = tanh_(xn + r * bhh[64 + l]);
    g_o32[i] = (1.f - z) * nst;
}

// ---------------- mean pool (two-pass) + classifier ----------------
__global__ void pool1(const int* __restrict__ gid) {
    __shared__ float s[8][32];
    __shared__ int   scnt[8];
    int g = blockIdx.x, part = blockIdx.y;
    int tid = threadIdx.x, lane = tid & 31, slot = tid >> 5;
    int base = part * (NNODES / 4), end = base + NNODES / 4;
    float acc = 0.f;
    int cnt = 0;
    for (int i = base + slot; i < end; i += 8) {
        if (gid[i] == g) {
            acc += g_o32[(size_t)i * 32 + lane];
            cnt++;
        }
    }
    s[slot][lane] = acc;
    if (lane == 0) scnt[slot] = cnt;
    __syncthreads();
    if (tid < 32) {
        float sum = 0.f; int tot = 0;
#pragma unroll
        for (int j = 0; j < 8; ++j) { sum += s[j][tid]; tot += scnt[j]; }
        g_pp[g][part][tid] = sum;
        if (tid == 0) g_pc[g][part] = tot;
    }
}

__global__ void pool2(const float* __restrict__ Wc, const float* __restrict__ bc,
                      float* __restrict__ out) {
    __shared__ float hg[32];
    int g = blockIdx.x, tid = threadIdx.x;
    float sum = g_pp[g][0][tid] + g_pp[g][1][tid] + g_pp[g][2][tid] + g_pp[g][3][tid];
    int tot = g_pc[g][0] + g_pc[g][1] + g_pc[g][2] + g_pc[g][3];
    hg[tid] = sum / (float)tot;
    __syncwarp();
    if (tid < NCLS) {
        float o = bc[tid];
#pragma unroll
        for (int k = 0; k < 32; ++k) o = fmaf(hg[k], Wc[k * NCLS + tid], o);
        out[g * NCLS + tid] = o;
    }
}

// ---------------- launch ----------------
extern "C" void kernel_launch(void* const* d_in, const int* in_sizes, int n_in,
                              void* d_out, int out_size) {
    const float* feature = (const float*)d_in[0];
    const int*   nbr     = (const int*)  d_in[1];
    const int*   deg     = (const int*)  d_in[2];
    const int*   gid     = (const int*)  d_in[3];
    const float* lWih    = (const float*)d_in[4];
    const float* lWhh    = (const float*)d_in[5];
    const float* lbih    = (const float*)d_in[6];
    const float* lbhh    = (const float*)d_in[7];
    const float* Wself   = (const float*)d_in[8];
    const float* Wneigh  = (const float*)d_in[9];
    const float* bsage   = (const float*)d_in[10];
    const float* Wgc     = (const float*)d_in[11];
    const float* bgc     = (const float*)d_in[12];
    const float* Wgru    = (const float*)d_in[13];
    const float* bihg    = (const float*)d_in[14];
    const float* bhhg    = (const float*)d_in[15];
    const float* Wcls    = (const float*)d_in[16];
    const float* bcls    = (const float*)d_in[17];
    float* out = (float*)d_out;

    const int smP = 65536 + 8704 + 1024;   // P split (NG=32)
    const int smS = 65536 + 17408 + 1024;  // SAGE 2-pass
    const int smG = 32768 + 8704 + 1024;   // GC
    const int smR = 24576 + 8704 + 1024;   // GRU N=96

    cudaFuncSetAttribute(hgemm, cudaFuncAttributeMaxDynamicSharedMemorySize, 90112);
    cudaFuncSetAttribute(lstm_mma, cudaFuncAttributeMaxDynamicSharedMemorySize, SM_TOTAL);

    void *pPb, *pFeatB, *pHtb, *pH1b, *pAggB, *pH2b, *pGh;
    void *pWfP, *pWfSelf, *pWfNeigh, *pWfGc, *pWfGru;
    cudaGetSymbolAddress(&pPb,     g_Pb);
    cudaGetSymbolAddress(&pFeatB,  g_featB);
    cudaGetSymbolAddress(&pHtb,    g_hTb);
    cudaGetSymbolAddress(&pH1b,    g_h1b);
    cudaGetSymbolAddress(&pAggB,   g_aggB);
    cudaGetSymbolAddress(&pH2b,    g_h2b);
    cudaGetSymbolAddress(&pGh,     g_gh);
    cudaGetSymbolAddress(&pWfP,    g_WfP4);
    cudaGetSymbolAddress(&pWfSelf, g_WfSelf4);
    cudaGetSymbolAddress(&pWfNeigh,g_WfNeigh4);
    cudaGetSymbolAddress(&pWfGc,   g_WfGc4);
    cudaGetSymbolAddress(&pWfGru,  g_WfGru4);

    prep_kernel<<<256, 256>>>(lWih, lWhh, lbih, lbhh, Wself, Wneigh, Wgc, Wgru);
    k_hist_f2b<<<148, 512>>>(deg, feature, (__nv_bfloat16*)pFeatB);
    // P = featB @ WihT(perm) -> bf16 [N,512], split x2
    hgemm<<<304, 256, smP>>>((const __nv_bfloat16*)pFeatB, nullptr,
                             (const uint4*)pWfP, nullptr, nullptr, pPb,
                             NNODES, 512, 0, 1, 2);
    k_offsets<<<1, 512>>>();
    k_scatter<<<98, 512>>>(deg);
    lstm_mma<<<152, 512, SM_TOTAL>>>(nbr);
    // h1 = relu(featB@Wself + hTb@Wneigh + b_sage) -> bf16
    hgemm<<<304, 256, smS>>>((const __nv_bfloat16*)pFeatB, (const __nv_bfloat16*)pHtb,
                             (const uint4*)pWfSelf, (const uint4*)pWfNeigh, bsage, pH1b,
                             NNODES, 128, 1, 1, 1);
    agg_kernel<<<(NNODES * 32 + 255) / 256, 256>>>(nbr, deg);
    // h2 = relu(aggB @ Wgc + b_gc) -> bf16
    hgemm<<<304, 256, smG>>>((const __nv_bfloat16*)pAggB, nullptr,
                             (const uint4*)pWfGc, nullptr, bgc, pH2b,
                             NNODES, 128, 1, 1, 1);
    // gh = h2b @ WgruT -> f32 [N,96]
    hgemm<<<304, 256, smR>>>((const __nv_bfloat16*)pH2b, nullptr,
                             (const uint4*)pWfGru, nullptr, nullptr, pGh,
                             NNODES, 96, 0, 0, 1);
    gruact<<<(NNODES * GRUH + 255) / 256, 256>>>(bihg, bhhg);
    pool1<<<dim3(NGRAPH, 4), 256>>>(gid);
    pool2<<<NGRAPH, 32>>>(Wcls, bcls, out);
}

// round 17
// speedup vs baseline: 1.1799x; 1.0494x over previous
#include <cuda_runtime.h>
#include <cuda_bf16.h>
#include <cstdint>

#define NNODES 50000
#define HID    128
#define MAXD   16
#define NGRAPH 50
#define NCLS   10
#define GRUH   32
#define MAXB   3400
#define PWARPS 128
#define PNODES 391   // ceil(NNODES / PWARPS)

// ---------------- scratch ----------------
__device__ __nv_bfloat16 g_Pb [(size_t)NNODES * 512];
__device__ __nv_bfloat16 g_featB[(size_t)NNODES * HID];
__device__ __nv_bfloat16 g_hTb [(size_t)NNODES * HID];
__device__ __nv_bfloat16 g_h1b [(size_t)NNODES * HID];
__device__ __nv_bfloat16 g_aggB[(size_t)NNODES * HID];
__device__ __nv_bfloat16 g_h2b [(size_t)NNODES * HID];
__device__ float g_gh [(size_t)NNODES * 96];
__device__ float g_o32[(size_t)NNODES * GRUH];
// fused (kt, kt+4) weight fragments
__device__ uint4 g_WfP4   [8192];
__device__ uint4 g_WfSelf4[2048];
__device__ uint4 g_WfNeigh4[2048];
__device__ uint4 g_WfGc4  [2048];
__device__ uint4 g_WfGru4 [1536];
__device__ uint4 g_Wfrag4[256 * 32];
__device__ float4 g_biasF[HID];
// pool partials (<=2 per warp)
__device__ int   g_partG[PWARPS * 2];
__device__ int   g_partC[PWARPS * 2];
__device__ float g_partA[PWARPS * 2][32];
// degree bucketing
__device__ int g_order[NNODES];
__device__ int g_histp[256][16];
__device__ int g_binoff[16];
__device__ int g_batch_start[MAXB];
__device__ int g_batch_info[MAXB];
__device__ int g_nbatch;

// ---------------- helpers ----------------
__device__ __forceinline__ float sigf(float x) {
    x = fminf(fmaxf(x, -30.f), 30.f);
    return __fdividef(1.f, 1.f + __expf(-x));
}
__device__ __forceinline__ float tanh_(float x) {
    x = fminf(fmaxf(x, -15.f), 15.f);
    float e = __expf(-2.f * x);
    return __fdividef(1.f - e, 1.f + e);
}
__device__ __forceinline__ float tanhap(float x) {
    float y; asm("tanh.approx.f32 %0, %1;" : "=f"(y) : "f"(x)); return y;
}
__device__ __forceinline__ float sigt(float x) { return fmaf(tanhap(x * 0.5f), 0.5f, 0.5f); }
__device__ __forceinline__ unsigned bf16u(float x) {
    __nv_bfloat16 b = __float2bfloat16(x);
    return (unsigned)*reinterpret_cast<unsigned short*>(&b);
}
__device__ __forceinline__ float blo(unsigned v) { return __uint_as_float(v << 16); }
__device__ __forceinline__ float bhi(unsigned v) { return __uint_as_float(v & 0xFFFF0000u); }

__host__ __device__ __forceinline__ int phys2row(int p) {
    int pb = p >> 4, rem = p & 15;
    int gamma, aa;
    if (rem < 8) { aa = rem >> 1; gamma = (rem & 1) ? 1 : 0; }
    else         { aa = (rem - 8) >> 1; gamma = (rem & 1) ? 3 : 2; }
    return gamma * HID + pb * 4 + aa;
}

__device__ __forceinline__ void mma16816(float* d, const unsigned* a, unsigned b0, unsigned b1) {
    asm volatile(
        "mma.sync.aligned.m16n8k16.row.col.f32.bf16.bf16.f32 "
        "{%0,%1,%2,%3}, {%4,%5,%6,%7}, {%8,%9}, {%0,%1,%2,%3};"
        : "+f"(d[0]), "+f"(d[1]), "+f"(d[2]), "+f"(d[3])
        : "r"(a[0]), "r"(a[1]), "r"(a[2]), "r"(a[3]), "r"(b0), "r"(b1));
}

__device__ __forceinline__ void ldsm4(unsigned* r, const void* p) {
    unsigned addr = (unsigned)__cvta_generic_to_shared(p);
    asm volatile("ldmatrix.sync.aligned.m8n8.x4.shared.b16 {%0,%1,%2,%3}, [%4];"
                 : "=r"(r[0]), "=r"(r[1]), "=r"(r[2]), "=r"(r[3]) : "r"(addr));
}

// ------- prep: weight packing + per-block degree hist + feature->bf16 -------
__global__ void prep_all(const float* __restrict__ Wih,
                         const float* __restrict__ Whh,
                         const float* __restrict__ bih,
                         const float* __restrict__ bhh,
                         const float* __restrict__ Wself,
                         const float* __restrict__ Wneigh,
                         const float* __restrict__ Wgc,
                         const float* __restrict__ Wgru,
                         const int* __restrict__ deg,
                         const float* __restrict__ feat,
                         __nv_bfloat16* __restrict__ featB) {
    __shared__ int h[16];
    if (threadIdx.x < 16) h[threadIdx.x] = 0;
    __syncthreads();
    int idx = blockIdx.x * blockDim.x + threadIdx.x;
    int l = idx & 31, t = idx >> 5;
    int stride = gridDim.x * blockDim.x;

    // degree histogram (per-block partial)
    for (int i = idx; i < NNODES; i += stride)
        atomicAdd(&h[deg[i] - 1], 1);
    // feature -> bf16
    for (int i = idx; i < NNODES * HID / 4; i += stride) {
        float4 v = ((const float4*)feat)[i];
        uint2 o;
        o.x = bf16u(v.x) | (bf16u(v.y) << 16);
        o.y = bf16u(v.z) | (bf16u(v.w) << 16);
        ((uint2*)featB)[i] = o;
    }

    if (idx < 8192) {
        int kt = t >> 6, gg = t & 63;
        int n = gg * 8 + (l >> 2);
        int r = phys2row(n) * HID;
        int ka = kt * 16 + (l & 3) * 2;
        int kb = ka + 64;
        uint4 v;
        v.x = bf16u(Wih[r + ka])     | (bf16u(Wih[r + ka + 1]) << 16);
        v.y = bf16u(Wih[r + ka + 8]) | (bf16u(Wih[r + ka + 9]) << 16);
        v.z = bf16u(Wih[r + kb])     | (bf16u(Wih[r + kb + 1]) << 16);
        v.w = bf16u(Wih[r + kb + 8]) | (bf16u(Wih[r + kb + 9]) << 16);
        g_WfP4[idx] = v;
    }
    if (idx < 2048) {
        int kt = t >> 4, gg = t & 15;
        int n = gg * 8 + (l >> 2);
        int ka = kt * 16 + (l & 3) * 2;
        int kb = ka + 64;
        uint4 v;
        v.x = bf16u(Wself[ka * HID + n])       | (bf16u(Wself[(ka + 1) * HID + n]) << 16);
        v.y = bf16u(Wself[(ka + 8) * HID + n]) | (bf16u(Wself[(ka + 9) * HID + n]) << 16);
        v.z = bf16u(Wself[kb * HID + n])       | (bf16u(Wself[(kb + 1) * HID + n]) << 16);
        v.w = bf16u(Wself[(kb + 8) * HID + n]) | (bf16u(Wself[(kb + 9) * HID + n]) << 16);
        g_WfSelf4[idx] = v;
        v.x = bf16u(Wneigh[ka * HID + n])       | (bf16u(Wneigh[(ka + 1) * HID + n]) << 16);
        v.y = bf16u(Wneigh[(ka + 8) * HID + n]) | (bf16u(Wneigh[(ka + 9) * HID + n]) << 16);
        v.z = bf16u(Wneigh[kb * HID + n])       | (bf16u(Wneigh[(kb + 1) * HID + n]) << 16);
        v.w = bf16u(Wneigh[(kb + 8) * HID + n]) | (bf16u(Wneigh[(kb + 9) * HID + n]) << 16);
        g_WfNeigh4[idx] = v;
        v.x = bf16u(Wgc[ka * HID + n])       | (bf16u(Wgc[(ka + 1) * HID + n]) << 16);
        v.y = bf16u(Wgc[(ka + 8) * HID + n]) | (bf16u(Wgc[(ka + 9) * HID + n]) << 16);
        v.z = bf16u(Wgc[kb * HID + n])       | (bf16u(Wgc[(kb + 1) * HID + n]) << 16);
        v.w = bf16u(Wgc[(kb + 8) * HID + n]) | (bf16u(Wgc[(kb + 9) * HID + n]) << 16);
        g_WfGc4[idx] = v;
    }
    if (idx < 1536) {
        int kt = t / 12, gg = t % 12;
        int n = gg * 8 + (l >> 2);
        int ka = kt * 16 + (l & 3) * 2;
        int kb = ka + 64;
        const float* wr = Wgru + (size_t)n * HID;
        uint4 v;
        v.x = bf16u(wr[ka])     | (bf16u(wr[ka + 1]) << 16);
        v.y = bf16u(wr[ka + 8]) | (bf16u(wr[ka + 9]) << 16);
        v.z = bf16u(wr[kb])     | (bf16u(wr[kb + 1]) << 16);
        v.w = bf16u(wr[kb + 8]) | (bf16u(wr[kb + 9]) << 16);
        g_WfGru4[idx] = v;
    }
    if (idx < 512 * 32) {
        int kt = t >> 6, ntg = t & 63;
        int p = ntg * 8 + (l >> 2);
        int wrow = phys2row(p);
        int k0 = kt * 16 + (l & 3) * 2;
        const float* wr = Whh + (size_t)wrow * HID;
        uint2 v;
        v.x = bf16u(wr[k0])     | (bf16u(wr[k0 + 1]) << 16);
        v.y = bf16u(wr[k0 + 8]) | (bf16u(wr[k0 + 9]) << 16);
        int chunk = ntg >> 4, nt = ntg & 15;
        int pp = nt >> 1, isO = nt & 1;
        int dst = (((kt << 5) | (chunk << 3) | pp) * 32 + l) * 2 + isO;
        ((uint2*)g_Wfrag4)[dst] = v;
    }
    if (idx < HID) {
        g_biasF[idx] = make_float4(bih[idx] + bhh[idx],
                                   bih[HID + idx] + bhh[HID + idx],
                                   bih[2 * HID + idx] + bhh[2 * HID + idx],
                                   bih[3 * HID + idx] + bhh[3 * HID + idx]);
    }
    __syncthreads();
    if (threadIdx.x < 16) g_histp[blockIdx.x][threadIdx.x] = h[threadIdx.x];
}

__global__ void k_offsets() {
    __shared__ int btot[16], binbase[16], bOffD[16];
    __shared__ int nbatch_s;
    int tid = threadIdx.x;
    if (tid < 16) {
        int s = 0;
        for (int blk = 0; blk < 256; ++blk) s += g_histp[blk][tid];
        btot[tid] = s;
    }
    __syncthreads();
    if (tid == 0) {
        int off = 0;
        for (int b = 0; b < 16; ++b) {
            binbase[b] = off;
            g_binoff[b] = off;
            off += btot[b];
        }
        int bo = 0;
        for (int b = 15; b >= 0; --b) { bOffD[b] = bo; bo += (btot[b] + 15) >> 4; }
        nbatch_s = bo;
        g_nbatch = bo;
    }
    __syncthreads();
    int nb = nbatch_s;
    for (int bi = tid; bi < nb; bi += blockDim.x) {
        int bin = 0;
#pragma unroll
        for (int b = 15; b >= 0; --b) {
            int nbb = (btot[b] + 15) >> 4;
            if (bi >= bOffD[b] && bi < bOffD[b] + nbb) { bin = b; break; }
        }
        int j = (bi - bOffD[bin]) * 16;
        g_batch_start[bi] = binbase[bin] + j;
        g_batch_info[bi]  = ((bin + 1) << 8) | min(16, btot[bin] - j);
    }
}

__global__ void k_scatter(const int* __restrict__ deg) {
    __shared__ int scnt[16], sbase[16], scur[16];
    int t = threadIdx.x;
    if (t < 16) { scnt[t] = 0; scur[t] = 0; }
    __syncthreads();
    int i = blockIdx.x * 512 + t;
    int d = -1;
    if (i < NNODES) { d = deg[i] - 1; atomicAdd(&scnt[d], 1); }
    __syncthreads();
    if (t < 16 && scnt[t] > 0) sbase[t] = atomicAdd(&g_binoff[t], scnt[t]);
    __syncthreads();
    if (i < NNODES) {
        int pos = sbase[d] + atomicAdd(&scur[d], 1);
        g_order[pos] = i;
    }
}

// ------- bf16 HMMA GEMM (proven config): smem-staged A + ldmatrix, fused uint4 B -------
#define AS 136

__global__ __launch_bounds__(256, 2)
void hgemm(const __nv_bfloat16* __restrict__ A1, const __nv_bfloat16* __restrict__ A2,
           const uint4* __restrict__ W1, const uint4* __restrict__ W2,
           const float* __restrict__ bias, void* __restrict__ out,
           int M, int N, int relu, int obf16, int splits) {
    extern __shared__ char sm[];
    int Nc = N / splits;
    int NG = Nc >> 3;
    int NGfull = N >> 3;
    int nw4 = 4 * NG * 32;
    int sp = blockIdx.x & (splits - 1);
    int cbase = sp * Nc;
    int nCTA = gridDim.x >> (splits - 1);
    int npass = (A2 != nullptr) ? 2 : 1;
    uint4* wf1 = (uint4*)sm;
    uint4* wf2 = wf1 + nw4;
    unsigned short* ast = (unsigned short*)(wf1 + (size_t)npass * nw4);
    float* bsm = (float*)(ast + npass * 32 * AS);

    int tid = threadIdx.x, wid = tid >> 5, lane = tid & 31;
    {
        for (int i = tid; i < nw4; i += 256) {
            int t2 = i >> 5, li = i & 31;
            int kt = t2 / NG, gg = t2 - kt * NG;
            int src = (kt * NGfull + sp * NG + gg) * 32 + li;
            wf1[i] = W1[src];
            if (npass == 2) wf2[i] = W2[src];
        }
    }
    if (bias) for (int i = tid; i < Nc; i += 256) bsm[i] = bias[cbase + i];

    int rh = wid & 1, cc = wid >> 1;
    int gpw = NG >> 2;
    int r0 = lane >> 2, q = lane & 3;
    int nbat = (M + 31) >> 5;
    int lrow = tid >> 3, lch = tid & 7;

    uint4 pf[2][2];
    int bi = blockIdx.x >> (splits - 1);
    if (bi < nbat) {
        int gr = min(bi * 32 + lrow, M - 1);
        const uint4* s = (const uint4*)(A1 + (size_t)gr * 128 + lch * 16);
        pf[0][0] = s[0]; pf[0][1] = s[1];
        if (npass == 2) {
            const uint4* s2 = (const uint4*)(A2 + (size_t)gr * 128 + lch * 16);
            pf[1][0] = s2[0]; pf[1][1] = s2[1];
        }
    }
    __syncthreads();

    for (; bi < nbat; bi += nCTA) {
        {
            uint4* d = (uint4*)(ast + lrow * AS + lch * 16);
            d[0] = pf[0][0]; d[1] = pf[0][1];
            if (npass == 2) {
                uint4* d2 = (uint4*)(ast + 32 * AS + lrow * AS + lch * 16);
                d2[0] = pf[1][0]; d2[1] = pf[1][1];
            }
        }
        __syncthreads();
        int bn = bi + nCTA;
        if (bn < nbat) {
            int gr = min(bn * 32 + lrow, M - 1);
            const uint4* s = (const uint4*)(A1 + (size_t)gr * 128 + lch * 16);
            pf[0][0] = s[0]; pf[0][1] = s[1];
            if (npass == 2) {
                const uint4* s2 = (const uint4*)(A2 + (size_t)gr * 128 + lch * 16);
                pf[1][0] = s2[0]; pf[1][1] = s2[1];
            }
        }
        unsigned a1[8][4], a2[8][4];
        {
            const unsigned short* abase = ast + (rh * 16 + (lane & 15)) * AS + ((lane >> 4) << 3);
#pragma unroll
            for (int kt = 0; kt < 8; ++kt) ldsm4(a1[kt], abase + kt * 16);
            if (npass == 2) {
                const unsigned short* ab2 = abase + 32 * AS;
#pragma unroll
                for (int kt = 0; kt < 8; ++kt) ldsm4(a2[kt], ab2 + kt * 16);
            }
        }
        int gr0b = bi * 32 + rh * 16 + r0;
        for (int g = 0; g < gpw; ++g) {
            int gg = cc * gpw + g;
            float acc[4] = {0.f, 0.f, 0.f, 0.f};
            float acb[4] = {0.f, 0.f, 0.f, 0.f};
#pragma unroll
            for (int kt = 0; kt < 4; ++kt) {
                uint4 b = wf1[(kt * NG + gg) * 32 + lane];
                mma16816(acc, a1[kt],     b.x, b.y);
                mma16816(acb, a1[kt + 4], b.z, b.w);
            }
            if (npass == 2) {
#pragma unroll
                for (int kt = 0; kt < 4; ++kt) {
                    uint4 b = wf2[(kt * NG + gg) * 32 + lane];
                    mma16816(acc, a2[kt],     b.x, b.y);
                    mma16816(acb, a2[kt + 4], b.z, b.w);
                }
            }
#pragma unroll
            for (int i = 0; i < 4; ++i) acc[i] += acb[i];
            int c0l = gg * 8 + 2 * q;
            int c0 = cbase + c0l;
            float b0 = 0.f, b1 = 0.f;
            if (bias) { b0 = bsm[c0l]; b1 = bsm[c0l + 1]; }
            float o0 = acc[0] + b0, o1 = acc[1] + b1, o2 = acc[2] + b0, o3 = acc[3] + b1;
            if (relu) {
                o0 = fmaxf(o0, 0.f); o1 = fmaxf(o1, 0.f);
                o2 = fmaxf(o2, 0.f); o3 = fmaxf(o3, 0.f);
            }
            int gr1 = gr0b + 8;
            if (obf16) {
                unsigned w0 = bf16u(o0) | (bf16u(o1) << 16);
                unsigned w1 = bf16u(o2) | (bf16u(o3) << 16);
                if (gr0b < M) *(unsigned*)((__nv_bfloat16*)out + (size_t)gr0b * N + c0) = w0;
                if (gr1  < M) *(unsigned*)((__nv_bfloat16*)out + (size_t)gr1  * N + c0) = w1;
            } else {
                if (gr0b < M) *(float2*)((float*)out + (size_t)gr0b * N + c0) = make_float2(o0, o1);
                if (gr1  < M) *(float2*)((float*)out + (size_t)gr1  * N + c0) = make_float2(o2, o3);
            }
        }
        __syncthreads();
    }
}

// ------- mma.sync LSTM: unchanged from R16 winner -------
#define LGROUPS 4
#define HSTRIDE 136
#define SM_WF    0
#define SM_BIAS  131072
#define SM_HSTG  133120
#define SM_NID   (SM_HSTG + 34816)
#define SM_USM   (SM_NID + 256)
#define SM_TOTAL (SM_USM + 4096)

__global__ __launch_bounds__(512, 1)
void lstm_mma(const int* __restrict__ nbr) {
    extern __shared__ char smr[];
    uint4*  wf  = (uint4*)(smr + SM_WF);
    float4* bsm = (float4*)(smr + SM_BIAS);
    __nv_bfloat16* hstg = (__nv_bfloat16*)(smr + SM_HSTG);
    int* nidA = (int*)(smr + SM_NID);
    int* usmA = (int*)(smr + SM_USM);

    int tid = threadIdx.x, wid = tid >> 5, lane = tid & 31;
    for (int i = tid; i < 256 * 32; i += 512) wf[i] = g_Wfrag4[i];
    if (tid < HID) bsm[tid] = g_biasF[tid];
    __syncthreads();

    int grp = wid >> 2, chunk = wid & 3;
    __nv_bfloat16* hs0 = hstg + grp * 2 * 16 * HSTRIDE;
    __nv_bfloat16* hs1 = hs0 + 16 * HSTRIDE;
    int* mynid = nidA + grp * 16;
    int* usm   = usmA + grp * 16 * MAXD;
    int r0 = lane >> 2, q = lane & 3;
    int barid = grp + 1;
    int nb = g_nbatch;
    const unsigned* PB = (const unsigned*)g_Pb;

    for (int b = blockIdx.x * LGROUPS + grp; b < nb; b += gridDim.x * LGROUPS) {
        asm volatile("bar.sync %0, %1;" :: "r"(barid), "r"(128) : "memory");
        int start = g_batch_start[b];
        int info  = g_batch_info[b];
        int dmax = info >> 8, cnt = info & 255;
        if (chunk == 0 && lane < 16) {
            int nid = g_order[start + min(lane, cnt - 1)];
            mynid[lane] = nid;
            const int4* src = (const int4*)(nbr + nid * MAXD);
            int4* dst = (int4*)(usm + lane * MAXD);
            dst[0] = src[0]; dst[1] = src[1]; dst[2] = src[2]; dst[3] = src[3];
        }
        asm volatile("bar.sync %0, %1;" :: "r"(barid), "r"(128) : "memory");

        float cst[16];
#pragma unroll
        for (int i = 0; i < 16; ++i) cst[i] = 0.f;

        unsigned pnl[16];
        {
            const unsigned* L = PB + (size_t)usm[r0 * MAXD] * 256;
#pragma unroll
            for (int nt = 0; nt < 16; ++nt) pnl[nt] = L[chunk * 64 + nt * 4 + q];
        }

        for (int t = 0; t < dmax; ++t) {
            asm volatile("bar.sync %0, %1;" :: "r"(barid), "r"(128) : "memory");
            const __nv_bfloat16* hsR = (t & 1) ? hs0 : hs1;
            __nv_bfloat16*       hsW = (t & 1) ? hs1 : hs0;

            unsigned a[8][4];
            if (t > 0) {
                const __nv_bfloat16* ab = hsR + (lane & 15) * HSTRIDE + ((lane >> 4) << 3);
#pragma unroll
                for (int kt = 0; kt < 8; ++kt) ldsm4(a[kt], ab + kt * 16);
            }
            unsigned pcl[16];
#pragma unroll
            for (int nt = 0; nt < 16; ++nt) pcl[nt] = pnl[nt];
            unsigned pch[16];
            {
                const unsigned* H = PB + (size_t)usm[(r0 + 8) * MAXD + t] * 256;
#pragma unroll
                for (int nt = 0; nt < 16; ++nt) pch[nt] = H[chunk * 64 + nt * 4 + q];
            }
            if (t + 1 < dmax) {
                const unsigned* L = PB + (size_t)usm[r0 * MAXD + t + 1] * 256;
#pragma unroll
                for (int nt = 0; nt < 16; ++nt) pnl[nt] = L[chunk * 64 + nt * 4 + q];
            }

            bool last = (t == dmax - 1);
#pragma unroll
            for (int p = 0; p < 8; ++p) {
                int J = chunk * 32 + p * 4 + q;
                float4 bs = bsm[J];
                float aE[4]  = {blo(pcl[2 * p]),     bhi(pcl[2 * p]),
                                blo(pch[2 * p]),     bhi(pch[2 * p])};
                float aO[4]  = {blo(pcl[2 * p + 1]), bhi(pcl[2 * p + 1]),
                                blo(pch[2 * p + 1]), bhi(pch[2 * p + 1])};
                float aE2[4] = {bs.x, bs.y, bs.x, bs.y};
                float aO2[4] = {bs.z, bs.w, bs.z, bs.w};
                if (t > 0) {
#pragma unroll
                    for (int kt = 0; kt < 4; ++kt) {
                        uint4 b0 = wf[((kt << 5) | (chunk << 3) | p) * 32 + lane];
                        uint4 b1 = wf[(((kt + 4) << 5) | (chunk << 3) | p) * 32 + lane];
                        mma16816(aE,  a[kt],     b0.x, b0.y);
                        mma16816(aO,  a[kt],     b0.z, b0.w);
                        mma16816(aE2, a[kt + 4], b1.x, b1.y);
                        mma16816(aO2, a[kt + 4], b1.z, b1.w);
                    }
                }
#pragma unroll
                for (int i = 0; i < 4; ++i) { aE[i] += aE2[i]; aO[i] += aO2[i]; }
                {
                    float cn = sigt(aE[1]) * cst[2 * p] + sigt(aE[0]) * tanhap(aO[0]);
                    cst[2 * p] = cn;
                    float h = sigt(aO[1]) * tanhap(cn);
                    if (!last) hsW[r0 * HSTRIDE + J] = __float2bfloat16(h);
                    else if (r0 < cnt) g_hTb[(size_t)mynid[r0] * HID + J] = __float2bfloat16(h);
                }
                {
                    float cn = sigt(aE[3]) * cst[2 * p + 1] + sigt(aE[2]) * tanhap(aO[2]);
                    cst[2 * p + 1] = cn;
                    float h = sigt(aO[3]) * tanhap(cn);
                    if (!last) hsW[(r0 + 8) * HSTRIDE + J] = __float2bfloat16(h);
                    else if (r0 + 8 < cnt) g_hTb[(size_t)mynid[r0 + 8] * HID + J] = __float2bfloat16(h);
                }
            }
        }
    }
}

// ---------------- GraphConv aggregate (bf16 in/out, 2x unrolled) ----------------
__global__ void agg_kernel(const int* __restrict__ nbr, const int* __restrict__ deg) {
    int wid  = (blockIdx.x * blockDim.x + threadIdx.x) >> 5;
    int lane = threadIdx.x & 31;
    if (wid >= NNODES) return;
    int d = deg[wid];
    const int* nb = nbr + wid * MAXD;
    float a0 = 0.f, a1 = 0.f, a2 = 0.f, a3 = 0.f;
    int t = 0;
    for (; t + 1 < d; t += 2) {
        int u0 = nb[t], u1 = nb[t + 1];
        float n0 = rsqrtf((float)max(deg[u0], 1));
        float n1 = rsqrtf((float)max(deg[u1], 1));
        uint2 v0 = *(const uint2*)(g_h1b + (size_t)u0 * 128 + lane * 4);
        uint2 v1 = *(const uint2*)(g_h1b + (size_t)u1 * 128 + lane * 4);
        a0 = fmaf(blo(v0.x), n0, a0); a1 = fmaf(bhi(v0.x), n0, a1);
        a2 = fmaf(blo(v0.y), n0, a2); a3 = fmaf(bhi(v0.y), n0, a3);
        a0 = fmaf(blo(v1.x), n1, a0); a1 = fmaf(bhi(v1.x), n1, a1);
        a2 = fmaf(blo(v1.y), n1, a2); a3 = fmaf(bhi(v1.y), n1, a3);
    }
    if (t < d) {
        int u = nb[t];
        float nu = rsqrtf((float)max(deg[u], 1));
        uint2 v = *(const uint2*)(g_h1b + (size_t)u * 128 + lane * 4);
        a0 = fmaf(blo(v.x), nu, a0); a1 = fmaf(bhi(v.x), nu, a1);
        a2 = fmaf(blo(v.y), nu, a2); a3 = fmaf(bhi(v.y), nu, a3);
    }
    float nn = rsqrtf((float)max(d, 1));
    uint2 o;
    o.x = bf16u(a0 * nn) | (bf16u(a1 * nn) << 16);
    o.y = bf16u(a2 * nn) | (bf16u(a3 * nn) << 16);
    *(uint2*)(g_aggB + (size_t)wid * 128 + lane * 4) = o;
}

// ---------------- GRU activation ----------------
__global__ void gruact(const float* __restrict__ bih, const float* __restrict__ bhh) {
    int i = blockIdx.x * blockDim.x + threadIdx.x;
    if (i >= NNODES * GRUH) return;
    int n = i >> 5, l = i & 31;
    const float* g = g_gh + (size_t)n * 96;
    float xr = g[l]      + bih[l];
    float xz = g[32 + l] + bih[32 + l];
    float xn = g[64 + l] + bih[64 + l];
    float r   = sigf(xr + bhh[l]);
    float z   = sigf(xz + bhh[32 + l]);
    float nst = tanh_(xn + r * bhh[64 + l]);
    g_o32[i] = (1.f - z) * nst;
}

// ------- pool: warp-contiguous scan (gid monotone => <=2 partials/warp) -------
__global__ void pool1(const int* __restrict__ gid) {
    int w = (blockIdx.x * blockDim.x + threadIdx.x) >> 5;
    int lane = threadIdx.x & 31;
    if (w >= PWARPS) return;
    int i0 = w * PNODES, i1 = min(i0 + PNODES, NNODES);
    // default-invalid second slot
    if (lane == 0) { g_partG[w * 2] = -1; g_partG[w * 2 + 1] = -1; }
    if (i0 >= NNODES) return;
    int curg = gid[i0];
    float acc = 0.f;
    int cnt = 0, slot = 0;
    for (int i = i0; i < i1; ++i) {
        int g = gid[i];
        if (g != curg) {
            g_partA[w * 2 + slot][lane] = acc;
            if (lane == 0) { g_partG[w * 2 + slot] = curg; g_partC[w * 2 + slot] = cnt; }
            slot = 1; acc = 0.f; cnt = 0; curg = g;
        }
        acc += g_o32[(size_t)i * 32 + lane];
        cnt++;
    }
    g_partA[w * 2 + slot][lane] = acc;
    if (lane == 0) { g_partG[w * 2 + slot] = curg; g_partC[w * 2 + slot] = cnt; }
}

__global__ void pool2(const float* __restrict__ Wc, const float* __restrict__ bc,
                      float* __restrict__ out) {
    __shared__ float hg[32];
    int g = blockIdx.x, tid = threadIdx.x;
    float sum = 0.f;
    int tot = 0;
    for (int s = 0; s < PWARPS * 2; ++s) {
        if (g_partG[s] == g) {
            sum += g_partA[s][tid];
            tot += g_partC[s];
        }
    }
    hg[tid] = sum / (float)tot;
    __syncwarp();
    if (tid < NCLS) {
        float o = bc[tid];
#pragma unroll
        for (int k = 0; k < 32; ++k) o = fmaf(hg[k], Wc[k * NCLS + tid], o);
        out[g * NCLS + tid] = o;
    }
}

// ---------------- launch ----------------
extern "C" void kernel_launch(void* const* d_in, const int* in_sizes, int n_in,
                              void* d_out, int out_size) {
    const float* feature = (const float*)d_in[0];
    const int*   nbr     = (const int*)  d_in[1];
    const int*   deg     = (const int*)  d_in[2];
    const int*   gid     = (const int*)  d_in[3];
    const float* lWih    = (const float*)d_in[4];
    const float* lWhh    = (const float*)d_in[5];
    const float* lbih    = (const float*)d_in[6];
    const float* lbhh    = (const float*)d_in[7];
    const float* Wself   = (const float*)d_in[8];
    const float* Wneigh  = (const float*)d_in[9];
    const float* bsage   = (const float*)d_in[10];
    const float* Wgc     = (const float*)d_in[11];
    const float* bgc     = (const float*)d_in[12];
    const float* Wgru    = (const float*)d_in[13];
    const float* bihg    = (const float*)d_in[14];
    const float* bhhg    = (const float*)d_in[15];
    const float* Wcls    = (const float*)d_in[16];
    const float* bcls    = (const float*)d_in[17];
    float* out = (float*)d_out;

    const int smP = 65536 + 8704 + 1024;   // P split (NG=32)
    const int smS = 65536 + 17408 + 1024;  // SAGE 2-pass
    const int smG = 32768 + 8704 + 1024;   // GC
    const int smR = 24576 + 8704 + 1024;   // GRU N=96

    cudaFuncSetAttribute(hgemm, cudaFuncAttributeMaxDynamicSharedMemorySize, 90112);
    cudaFuncSetAttribute(lstm_mma, cudaFuncAttributeMaxDynamicSharedMemorySize, SM_TOTAL);

    void *pPb, *pFeatB, *pHtb, *pH1b, *pAggB, *pH2b, *pGh;
    void *pWfP, *pWfSelf, *pWfNeigh, *pWfGc, *pWfGru;
    cudaGetSymbolAddress(&pPb,     g_Pb);
    cudaGetSymbolAddress(&pFeatB,  g_featB);
    cudaGetSymbolAddress(&pHtb,    g_hTb);
    cudaGetSymbolAddress(&pH1b,    g_h1b);
    cudaGetSymbolAddress(&pAggB,   g_aggB);
    cudaGetSymbolAddress(&pH2b,    g_h2b);
    cudaGetSymbolAddress(&pGh,     g_gh);
    cudaGetSymbolAddress(&pWfP,    g_WfP4);
    cudaGetSymbolAddress(&pWfSelf, g_WfSelf4);
    cudaGetSymbolAddress(&pWfNeigh,g_WfNeigh4);
    cudaGetSymbolAddress(&pWfGc,   g_WfGc4);
    cudaGetSymbolAddress(&pWfGru,  g_WfGru4);

    // 1. prep (weights + per-block hist + f2b)
    prep_all<<<256, 256>>>(lWih, lWhh, lbih, lbhh, Wself, Wneigh, Wgc, Wgru,
                           deg, feature, (__nv_bfloat16*)pFeatB);
    // 2. P = featB @ WihT(perm) -> bf16 [N,512], split x2
    hgemm<<<304, 256, smP>>>((const __nv_bfloat16*)pFeatB, nullptr,
                             (const uint4*)pWfP, nullptr, nullptr, pPb,
                             NNODES, 512, 0, 1, 2);
    k_offsets<<<1, 512>>>();
    k_scatter<<<98, 512>>>(deg);
    lstm_mma<<<152, 512, SM_TOTAL>>>(nbr);
    // h1 = relu(featB@Wself + hTb@Wneigh + b_sage) -> bf16
    hgemm<<<304, 256, smS>>>((const __nv_bfloat16*)pFeatB, (const __nv_bfloat16*)pHtb,
                             (const uint4*)pWfSelf, (const uint4*)pWfNeigh, bsage, pH1b,
                             NNODES, 128, 1, 1, 1);
    agg_kernel<<<(NNODES * 32 + 255) / 256, 256>>>(nbr, deg);
    // h2 = relu(aggB @ Wgc + b_gc) -> bf16
    hgemm<<<304, 256, smG>>>((const __nv_bfloat16*)pAggB, nullptr,
                             (const uint4*)pWfGc, nullptr, bgc, pH2b,
                             NNODES, 128, 1, 1, 1);
    // gh = h2b @ WgruT -> f32 [N,96]
    hgemm<<<304, 256, smR>>>((const __nv_bfloat16*)pH2b, nullptr,
                             (const uint4*)pWfGru, nullptr, nullptr, pGh,
                             NNODES, 96, 0, 0, 1);
    gruact<<<(NNODES * GRUH + 255) / 256, 256>>>(bihg, bhhg);
    pool1<<<(PWARPS * 32 + 255) / 256, 256>>>(gid);
    pool2<<<NGRAPH, 32>>>(Wcls, bcls, out);
}